// round 1
// baseline (speedup 1.0000x reference)
#include <cuda_runtime.h>
#include <math_constants.h>

#define D_MODEL 1024
#define N_HEADS 16
#define HEAD_DIM 64
#define SEQ 1024
#define BATCH 32
#define M_TOK (BATCH * SEQ)   // 32768 tokens

// Scratch (alloc-free rule: __device__ globals). 4 x 128 MB.
__device__ float g_Q[(size_t)M_TOK * D_MODEL];
__device__ float g_K[(size_t)M_TOK * D_MODEL];
__device__ float g_V[(size_t)M_TOK * D_MODEL];
__device__ float g_C[(size_t)M_TOK * D_MODEL];

// ---------------------------------------------------------------------------
// SGEMM: C[M,N] = A[M,K] * B[K,N], all row-major. 128x128 tile, BK=16,
// 256 threads, 8x8 per thread, float4 everywhere. M%128==0, N%128==0, K%16==0.
// ---------------------------------------------------------------------------
__global__ __launch_bounds__(256, 2)
void sgemm128(const float* __restrict__ A, const float* __restrict__ B,
              float* __restrict__ C, int M, int N, int K)
{
    __shared__ float As[16][128];   // [k][m]  (A transposed on store)
    __shared__ float Bs[16][128];   // [k][n]

    const int tid = threadIdx.x;
    const int tx = tid & 15, ty = tid >> 4;
    const int row0 = blockIdx.y * 128;
    const int col0 = blockIdx.x * 128;

    float acc[8][8];
#pragma unroll
    for (int r = 0; r < 8; r++)
#pragma unroll
        for (int c = 0; c < 8; c++) acc[r][c] = 0.f;

    for (int k0 = 0; k0 < K; k0 += 16) {
        // Load A tile 128x16 (2 float4 per thread), store transposed.
#pragma unroll
        for (int i = 0; i < 2; i++) {
            int idx = tid + i * 256;        // 0..511
            int row = idx >> 2;             // 0..127
            int kc  = (idx & 3) << 2;       // 0,4,8,12
            float4 v = *(const float4*)(A + (size_t)(row0 + row) * K + k0 + kc);
            As[kc + 0][row] = v.x;
            As[kc + 1][row] = v.y;
            As[kc + 2][row] = v.z;
            As[kc + 3][row] = v.w;
        }
        // Load B tile 16x128 (2 float4 per thread), natural layout.
#pragma unroll
        for (int i = 0; i < 2; i++) {
            int idx = tid + i * 256;        // 0..511
            int kr  = idx >> 5;             // 0..15
            int col = (idx & 31) << 2;      // 0..124
            *(float4*)&Bs[kr][col] =
                *(const float4*)(B + (size_t)(k0 + kr) * N + col0 + col);
        }
        __syncthreads();

#pragma unroll
        for (int k = 0; k < 16; k++) {
            float a[8], b[8];
            *(float4*)&a[0] = *(float4*)&As[k][ty * 8];
            *(float4*)&a[4] = *(float4*)&As[k][ty * 8 + 4];
            *(float4*)&b[0] = *(float4*)&Bs[k][tx * 8];
            *(float4*)&b[4] = *(float4*)&Bs[k][tx * 8 + 4];
#pragma unroll
            for (int r = 0; r < 8; r++)
#pragma unroll
                for (int c = 0; c < 8; c++)
                    acc[r][c] = fmaf(a[r], b[c], acc[r][c]);
        }
        __syncthreads();
    }

#pragma unroll
    for (int r = 0; r < 8; r++) {
        float* cp = C + (size_t)(row0 + ty * 8 + r) * N + col0 + tx * 8;
        *(float4*)cp       = make_float4(acc[r][0], acc[r][1], acc[r][2], acc[r][3]);
        *(float4*)(cp + 4) = make_float4(acc[r][4], acc[r][5], acc[r][6], acc[r][7]);
    }
}

// ---------------------------------------------------------------------------
// Flash attention, fp32. One block per (b, h, 128-query-row tile).
// KV tiles of 64 rows. 256 threads as 16x16; thread owns 8 q-rows x 4 cols.
// Online softmax; per-row stats reduced across 16 lanes (same ty) by shuffles.
// ---------------------------------------------------------------------------
#define ATTN_SMEM_FLOATS (64 * 128 + 64 * 64 + 64 * 64 + 128 * 68)
#define ATTN_SMEM_BYTES  (ATTN_SMEM_FLOATS * 4)

__global__ __launch_bounds__(256, 2)
void attn128(const float* __restrict__ Q, const float* __restrict__ K,
             const float* __restrict__ V, float* __restrict__ O)
{
    extern __shared__ float sm[];
    float* Qst = sm;                  // [d][m], stride 128 (Q^T, pre-scaled)
    float* Kst = Qst + 64 * 128;      // [d][n], stride 64  (K^T)
    float* Vs  = Kst + 64 * 64;       // [n][d], stride 64
    float* Ps  = Vs  + 64 * 64;       // [m][n], stride 68 (padded)

    const int tid = threadIdx.x;
    const int tx = tid & 15, ty = tid >> 4;
    const int bh = blockIdx.y;
    const int b = bh >> 4, h = bh & 15;
    const int q0 = blockIdx.x * 128;

    const float* Qb = Q + (size_t)b * SEQ * D_MODEL + h * HEAD_DIM;
    const float* Kb = K + (size_t)b * SEQ * D_MODEL + h * HEAD_DIM;
    const float* Vb = V + (size_t)b * SEQ * D_MODEL + h * HEAD_DIM;

    // Load + transpose + scale Q tile: 128 rows x 64 dims.
#pragma unroll
    for (int i = 0; i < 8; i++) {
        int idx = tid + i * 256;       // 0..2047
        int m  = idx >> 4;             // 0..127
        int d4 = (idx & 15) << 2;      // 0..60
        float4 v = *(const float4*)(Qb + (size_t)(q0 + m) * D_MODEL + d4);
        Qst[(d4 + 0) * 128 + m] = v.x * 0.125f;
        Qst[(d4 + 1) * 128 + m] = v.y * 0.125f;
        Qst[(d4 + 2) * 128 + m] = v.z * 0.125f;
        Qst[(d4 + 3) * 128 + m] = v.w * 0.125f;
    }

    float o[8][4];
    float mrow[8], lrow[8];
#pragma unroll
    for (int r = 0; r < 8; r++) {
        mrow[r] = -CUDART_INF_F;
        lrow[r] = 0.f;
        o[r][0] = o[r][1] = o[r][2] = o[r][3] = 0.f;
    }

    for (int j = 0; j < SEQ / 64; j++) {
        int n0 = j * 64;
        // Load K (transposed) and V (natural) tiles: 64 rows x 64 dims each.
#pragma unroll
        for (int i = 0; i < 4; i++) {
            int idx = tid + i * 256;    // 0..1023
            int n  = idx >> 4;          // 0..63
            int d4 = (idx & 15) << 2;   // 0..60
            float4 kv = *(const float4*)(Kb + (size_t)(n0 + n) * D_MODEL + d4);
            Kst[(d4 + 0) * 64 + n] = kv.x;
            Kst[(d4 + 1) * 64 + n] = kv.y;
            Kst[(d4 + 2) * 64 + n] = kv.z;
            Kst[(d4 + 3) * 64 + n] = kv.w;
            *(float4*)&Vs[n * 64 + d4] =
                *(const float4*)(Vb + (size_t)(n0 + n) * D_MODEL + d4);
        }
        __syncthreads();

        // S = (Q*scale) K^T : thread computes 8x4 of the 128x64 tile.
        float s[8][4];
#pragma unroll
        for (int r = 0; r < 8; r++)
            s[r][0] = s[r][1] = s[r][2] = s[r][3] = 0.f;
#pragma unroll
        for (int d = 0; d < 64; d++) {
            float qv[8], kv[4];
            *(float4*)&qv[0] = *(float4*)&Qst[d * 128 + ty * 8];
            *(float4*)&qv[4] = *(float4*)&Qst[d * 128 + ty * 8 + 4];
            *(float4*)&kv[0] = *(float4*)&Kst[d * 64 + tx * 4];
#pragma unroll
            for (int r = 0; r < 8; r++)
#pragma unroll
                for (int c = 0; c < 4; c++)
                    s[r][c] = fmaf(qv[r], kv[c], s[r][c]);
        }

        // Online softmax: row r lives on the 16 lanes sharing ty (xor 1,2,4,8).
#pragma unroll
        for (int r = 0; r < 8; r++) {
            float mx = fmaxf(fmaxf(s[r][0], s[r][1]), fmaxf(s[r][2], s[r][3]));
#pragma unroll
            for (int off = 1; off < 16; off <<= 1)
                mx = fmaxf(mx, __shfl_xor_sync(0xffffffffu, mx, off));
            float mn = fmaxf(mrow[r], mx);
            float alpha = __expf(mrow[r] - mn);
            mrow[r] = mn;
            float p0 = __expf(s[r][0] - mn);
            float p1 = __expf(s[r][1] - mn);
            float p2 = __expf(s[r][2] - mn);
            float p3 = __expf(s[r][3] - mn);
            float rs = (p0 + p1) + (p2 + p3);
#pragma unroll
            for (int off = 1; off < 16; off <<= 1)
                rs += __shfl_xor_sync(0xffffffffu, rs, off);
            lrow[r] = lrow[r] * alpha + rs;
            o[r][0] *= alpha; o[r][1] *= alpha; o[r][2] *= alpha; o[r][3] *= alpha;
            *(float4*)&Ps[(ty * 8 + r) * 68 + tx * 4] = make_float4(p0, p1, p2, p3);
        }
        __syncthreads();

        // O += P V : thread computes 8x4 of the 128x64 output tile.
#pragma unroll
        for (int n4 = 0; n4 < 16; n4++) {
            float p[8][4], v4[4][4];
#pragma unroll
            for (int r = 0; r < 8; r++)
                *(float4*)&p[r][0] = *(float4*)&Ps[(ty * 8 + r) * 68 + n4 * 4];
#pragma unroll
            for (int i = 0; i < 4; i++)
                *(float4*)&v4[i][0] = *(float4*)&Vs[(n4 * 4 + i) * 64 + tx * 4];
#pragma unroll
            for (int r = 0; r < 8; r++)
#pragma unroll
                for (int i = 0; i < 4; i++)
#pragma unroll
                    for (int c = 0; c < 4; c++)
                        o[r][c] = fmaf(p[r][i], v4[i][c], o[r][c]);
        }
        __syncthreads();
    }

    // Normalize and store context (same [B,S,H,Hd] contiguous layout).
#pragma unroll
    for (int r = 0; r < 8; r++) {
        float inv = 1.0f / lrow[r];
        int sidx = q0 + ty * 8 + r;
        float* op = O + (size_t)b * SEQ * D_MODEL + (size_t)sidx * D_MODEL
                      + h * HEAD_DIM + tx * 4;
        *(float4*)op = make_float4(o[r][0] * inv, o[r][1] * inv,
                                   o[r][2] * inv, o[r][3] * inv);
    }
}

// ---------------------------------------------------------------------------
// Launch: 3 projection GEMMs -> flash attention -> output GEMM.
// All default-stream kernel launches: graph-capturable, alloc-free.
// ---------------------------------------------------------------------------
extern "C" void kernel_launch(void* const* d_in, const int* in_sizes, int n_in,
                              void* d_out, int out_size)
{
    const float* x  = (const float*)d_in[0];
    const float* Wq = (const float*)d_in[1];
    const float* Wk = (const float*)d_in[2];
    const float* Wv = (const float*)d_in[3];
    const float* Wo = (const float*)d_in[4];
    float* out = (float*)d_out;

    float *Qp, *Kp, *Vp, *Cp;
    cudaGetSymbolAddress((void**)&Qp, g_Q);
    cudaGetSymbolAddress((void**)&Kp, g_K);
    cudaGetSymbolAddress((void**)&Vp, g_V);
    cudaGetSymbolAddress((void**)&Cp, g_C);

    cudaFuncSetAttribute(attn128, cudaFuncAttributeMaxDynamicSharedMemorySize,
                         ATTN_SMEM_BYTES);

    dim3 gGemm(D_MODEL / 128, M_TOK / 128);   // (8, 256)
    sgemm128<<<gGemm, 256>>>(x, Wq, Qp, M_TOK, D_MODEL, D_MODEL);
    sgemm128<<<gGemm, 256>>>(x, Wk, Kp, M_TOK, D_MODEL, D_MODEL);
    sgemm128<<<gGemm, 256>>>(x, Wv, Vp, M_TOK, D_MODEL, D_MODEL);

    dim3 gAttn(SEQ / 128, BATCH * N_HEADS);   // (8, 512)
    attn128<<<gAttn, 256, ATTN_SMEM_BYTES>>>(Qp, Kp, Vp, Cp);

    sgemm128<<<gGemm, 256>>>(Cp, Wo, out, M_TOK, D_MODEL, D_MODEL);
}

// round 3
// speedup vs baseline: 1.5249x; 1.5249x over previous
#include <cuda_runtime.h>
#include <cuda_bf16.h>
#include <math_constants.h>
#include <cstdint>

#define D_MODEL 1024
#define N_HEADS 16
#define HEAD_DIM 64
#define SEQ 1024
#define BATCH 32
#define M_TOK (BATCH * SEQ)   // 32768 tokens

// ---------------------------------------------------------------------------
// Scratch (alloc-free rule: __device__ globals).
// ---------------------------------------------------------------------------
__device__ float g_Q[(size_t)M_TOK * D_MODEL];
__device__ float g_K[(size_t)M_TOK * D_MODEL];
__device__ float g_V[(size_t)M_TOK * D_MODEL];
__device__ float g_C[(size_t)M_TOK * D_MODEL];
__device__ __nv_bfloat16 g_xhi[(size_t)M_TOK * D_MODEL];
__device__ __nv_bfloat16 g_xlo[(size_t)M_TOK * D_MODEL];
__device__ __nv_bfloat16 g_wthi[(size_t)4 * D_MODEL * D_MODEL];
__device__ __nv_bfloat16 g_wtlo[(size_t)4 * D_MODEL * D_MODEL];

// ---------------------------------------------------------------------------
// PTX helpers — ONLY non-suffixed (plain compute_103-legal) instructions:
// mma.sync / ldmatrix / cp.async. No tcgen05, no TMA.
// ---------------------------------------------------------------------------
__device__ __forceinline__ uint32_t smem_to_u32(const void* p) {
    uint32_t a;
    asm("{ .reg .u64 t; cvta.to.shared.u64 t, %1; cvt.u32.u64 %0, t; }" : "=r"(a) : "l"(p));
    return a;
}

#define CP_ASYNC16(sa, gp) \
    asm volatile("cp.async.cg.shared.global [%0], [%1], 16;" :: "r"(sa), "l"(gp))
#define CP_COMMIT() asm volatile("cp.async.commit_group;" ::: "memory")
#define CP_WAIT1()  asm volatile("cp.async.wait_group 1;" ::: "memory")
#define CP_WAIT0()  asm volatile("cp.async.wait_group 0;" ::: "memory")

#define LDSM_X4(r, a) \
    asm volatile("ldmatrix.sync.aligned.m8n8.x4.shared.b16 {%0,%1,%2,%3}, [%4];" \
        : "=r"((r)[0]), "=r"((r)[1]), "=r"((r)[2]), "=r"((r)[3]) : "r"(a))

#define MMA16816(c, a, b0v, b1v) \
    asm volatile("mma.sync.aligned.m16n8k16.row.col.f32.bf16.bf16.f32 " \
        "{%0,%1,%2,%3}, {%4,%5,%6,%7}, {%8,%9}, {%0,%1,%2,%3};" \
        : "+f"((c)[0]), "+f"((c)[1]), "+f"((c)[2]), "+f"((c)[3]) \
        : "r"((a)[0]), "r"((a)[1]), "r"((a)[2]), "r"((a)[3]), "r"(b0v), "r"(b1v))

// ---------------------------------------------------------------------------
// GEMM: C[M,N] = A[M,K] * B[N,K]^T, bf16x3 via mma.sync m16n8k16, fp32 accum.
// Block 128x128, 8 warps (2 x 4), warp tile 64x32. K-chunk 32, double buffer.
// Smem rows: 32 bf16 = 64B data padded to 80B -> conflict-free ldmatrix.
// ---------------------------------------------------------------------------
#define PADB 80
#define STAGE_A (128 * PADB)              // 10240 B per operand buffer
#define STAGE_BYTES (4 * STAGE_A)         // Ahi, Alo, Bhi, Blo
#define GEMM_SMEM (2 * STAGE_BYTES)       // 81920 B

__global__ __launch_bounds__(256, 1)
void gemm_mma_bf16x3(const __nv_bfloat16* __restrict__ Ahi, const __nv_bfloat16* __restrict__ Alo,
                     const __nv_bfloat16* __restrict__ Bhi, const __nv_bfloat16* __restrict__ Blo,
                     float* __restrict__ C, int M, int N, int K)
{
    extern __shared__ char smc[];
    const uint32_t sbase = smem_to_u32(smc);
    const int tid = threadIdx.x;
    const int lane = tid & 31, wid = tid >> 5;
    const int wm = wid >> 2, wn = wid & 3;           // warp grid 2 x 4
    const int m0 = blockIdx.y * 128, n0 = blockIdx.x * 128;

    float acc[4][4][4];
#pragma unroll
    for (int i = 0; i < 4; i++)
#pragma unroll
        for (int j = 0; j < 4; j++)
#pragma unroll
            for (int r = 0; r < 4; r++) acc[i][j][r] = 0.f;

    // ldmatrix per-lane base offsets (bytes) within a stage buffer.
    // A (m16k16 x4): row = warp_m*64 + (lane&15), kbyte = ((lane>>4)&1)*16
    const uint32_t aoff = (uint32_t)((wm * 64 + (lane & 15)) * PADB + ((lane >> 4) & 1) * 16);
    // B (two n8k16 per x4): row = warp_n*32 + (lane&7) + ((lane>>4)&1)*8, kbyte = ((lane>>3)&1)*16
    const uint32_t boff = (uint32_t)((wn * 32 + (lane & 7) + ((lane >> 4) & 1) * 8) * PADB
                                     + ((lane >> 3) & 1) * 16);

    auto load_stage = [&](int ch, int st) {
        const uint32_t sb = sbase + st * STAGE_BYTES;
        const size_t k0 = (size_t)ch * 32;
#pragma unroll
        for (int i = 0; i < 2; i++) {
            int s = tid + 256 * i;           // 0..511 : 128 rows x 4 16B segs
            int row = s >> 2, c = s & 3;
            uint32_t so = (uint32_t)(row * PADB + c * 16);
            size_t ga = ((size_t)(m0 + row) * K + k0) * 2 + c * 16;
            size_t gb = ((size_t)(n0 + row) * K + k0) * 2 + c * 16;
            CP_ASYNC16(sb + so,               (const char*)Ahi + ga);
            CP_ASYNC16(sb + STAGE_A + so,     (const char*)Alo + ga);
            CP_ASYNC16(sb + 2 * STAGE_A + so, (const char*)Bhi + gb);
            CP_ASYNC16(sb + 3 * STAGE_A + so, (const char*)Blo + gb);
        }
        CP_COMMIT();
    };

    const int NC = K / 32;
    load_stage(0, 0);

#pragma unroll 1
    for (int ch = 0; ch < NC; ch++) {
        const int st = ch & 1;
        if (ch + 1 < NC) { load_stage(ch + 1, st ^ 1); CP_WAIT1(); }
        else             { CP_WAIT0(); }
        __syncthreads();

        const uint32_t sb = sbase + st * STAGE_BYTES;
#pragma unroll
        for (int ks = 0; ks < 2; ks++) {
            const uint32_t kb = ks * 32;     // 16 bf16 = 32 bytes
            uint32_t ah[4][4], al[4][4], bh[2][4], bl[2][4];
#pragma unroll
            for (int i = 0; i < 4; i++) {
                LDSM_X4(ah[i], sb + aoff + i * (16 * PADB) + kb);
                LDSM_X4(al[i], sb + STAGE_A + aoff + i * (16 * PADB) + kb);
            }
#pragma unroll
            for (int j = 0; j < 2; j++) {
                LDSM_X4(bh[j], sb + 2 * STAGE_A + boff + j * (16 * PADB) + kb);
                LDSM_X4(bl[j], sb + 3 * STAGE_A + boff + j * (16 * PADB) + kb);
            }
#pragma unroll
            for (int i = 0; i < 4; i++)
#pragma unroll
                for (int j8 = 0; j8 < 4; j8++) {
                    const int jj = j8 >> 1, h = (j8 & 1) * 2;
                    MMA16816(acc[i][j8], ah[i], bh[jj][h], bh[jj][h + 1]);
                    MMA16816(acc[i][j8], al[i], bh[jj][h], bh[jj][h + 1]);
                    MMA16816(acc[i][j8], ah[i], bl[jj][h], bl[jj][h + 1]);
                }
        }
        __syncthreads();
    }

    // Epilogue: c frag m16n8 -> rows (lane>>2, +8), cols (lane&3)*2 + {0,1}
    const int r = lane >> 2, cl = (lane & 3) * 2;
#pragma unroll
    for (int i = 0; i < 4; i++)
#pragma unroll
        for (int j8 = 0; j8 < 4; j8++) {
            int row = m0 + wm * 64 + i * 16 + r;
            int col = n0 + wn * 32 + j8 * 8 + cl;
            *(float2*)(C + (size_t)row * N + col) =
                make_float2(acc[i][j8][0], acc[i][j8][1]);
            *(float2*)(C + (size_t)(row + 8) * N + col) =
                make_float2(acc[i][j8][2], acc[i][j8][3]);
        }
}

// ---------------------------------------------------------------------------
// Split fp32 -> (hi, lo) bf16, elementwise.
// ---------------------------------------------------------------------------
__global__ void k_split(const float4* __restrict__ in, uint2* __restrict__ hi,
                        uint2* __restrict__ lo, int n4)
{
    int i = blockIdx.x * blockDim.x + threadIdx.x;
    if (i >= n4) return;
    float4 v = in[i];
    float f[4] = {v.x, v.y, v.z, v.w};
    __nv_bfloat16 h[4], l[4];
#pragma unroll
    for (int j = 0; j < 4; j++) {
        h[j] = __float2bfloat16_rn(f[j]);
        l[j] = __float2bfloat16_rn(f[j] - __bfloat162float(h[j]));
    }
    hi[i] = *(uint2*)h;
    lo[i] = *(uint2*)l;
}

// Transpose + split weights: W[K,N] fp32 -> Wt_hi/lo[N,K] bf16.
__global__ void k_wsplit(const float* __restrict__ W, __nv_bfloat16* __restrict__ Th,
                         __nv_bfloat16* __restrict__ Tl)
{
    __shared__ float t[32][33];
    int k0 = blockIdx.x * 32, n0 = blockIdx.y * 32;
    int tx = threadIdx.x, ty = threadIdx.y;  // 32 x 8
#pragma unroll
    for (int i = 0; i < 4; i++)
        t[ty + 8 * i][tx] = W[(size_t)(k0 + ty + 8 * i) * D_MODEL + n0 + tx];
    __syncthreads();
#pragma unroll
    for (int i = 0; i < 4; i++) {
        float v = t[tx][ty + 8 * i];
        __nv_bfloat16 h = __float2bfloat16_rn(v);
        __nv_bfloat16 l = __float2bfloat16_rn(v - __bfloat162float(h));
        size_t o = (size_t)(n0 + ty + 8 * i) * D_MODEL + k0 + tx;
        Th[o] = h;
        Tl[o] = l;
    }
}

// ---------------------------------------------------------------------------
// Flash attention, fp32 (unchanged, known-good).
// ---------------------------------------------------------------------------
#define ATTN_SMEM_FLOATS (64 * 128 + 64 * 64 + 64 * 64 + 128 * 68)
#define ATTN_SMEM_BYTES  (ATTN_SMEM_FLOATS * 4)

__global__ __launch_bounds__(256, 2)
void attn128(const float* __restrict__ Q, const float* __restrict__ K,
             const float* __restrict__ V, float* __restrict__ O)
{
    extern __shared__ float sm[];
    float* Qst = sm;
    float* Kst = Qst + 64 * 128;
    float* Vs  = Kst + 64 * 64;
    float* Ps  = Vs  + 64 * 64;

    const int tid = threadIdx.x;
    const int tx = tid & 15, ty = tid >> 4;
    const int bh = blockIdx.y;
    const int b = bh >> 4, h = bh & 15;
    const int q0 = blockIdx.x * 128;

    const float* Qb = Q + (size_t)b * SEQ * D_MODEL + h * HEAD_DIM;
    const float* Kb = K + (size_t)b * SEQ * D_MODEL + h * HEAD_DIM;
    const float* Vb = V + (size_t)b * SEQ * D_MODEL + h * HEAD_DIM;

#pragma unroll
    for (int i = 0; i < 8; i++) {
        int idx = tid + i * 256;
        int m  = idx >> 4;
        int d4 = (idx & 15) << 2;
        float4 v = *(const float4*)(Qb + (size_t)(q0 + m) * D_MODEL + d4);
        Qst[(d4 + 0) * 128 + m] = v.x * 0.125f;
        Qst[(d4 + 1) * 128 + m] = v.y * 0.125f;
        Qst[(d4 + 2) * 128 + m] = v.z * 0.125f;
        Qst[(d4 + 3) * 128 + m] = v.w * 0.125f;
    }

    float o[8][4];
    float mrow[8], lrow[8];
#pragma unroll
    for (int r = 0; r < 8; r++) {
        mrow[r] = -CUDART_INF_F;
        lrow[r] = 0.f;
        o[r][0] = o[r][1] = o[r][2] = o[r][3] = 0.f;
    }

    for (int j = 0; j < SEQ / 64; j++) {
        int n0 = j * 64;
#pragma unroll
        for (int i = 0; i < 4; i++) {
            int idx = tid + i * 256;
            int n  = idx >> 4;
            int d4 = (idx & 15) << 2;
            float4 kv = *(const float4*)(Kb + (size_t)(n0 + n) * D_MODEL + d4);
            Kst[(d4 + 0) * 64 + n] = kv.x;
            Kst[(d4 + 1) * 64 + n] = kv.y;
            Kst[(d4 + 2) * 64 + n] = kv.z;
            Kst[(d4 + 3) * 64 + n] = kv.w;
            *(float4*)&Vs[n * 64 + d4] =
                *(const float4*)(Vb + (size_t)(n0 + n) * D_MODEL + d4);
        }
        __syncthreads();

        float s[8][4];
#pragma unroll
        for (int r = 0; r < 8; r++)
            s[r][0] = s[r][1] = s[r][2] = s[r][3] = 0.f;
#pragma unroll
        for (int d = 0; d < 64; d++) {
            float qv[8], kv[4];
            *(float4*)&qv[0] = *(float4*)&Qst[d * 128 + ty * 8];
            *(float4*)&qv[4] = *(float4*)&Qst[d * 128 + ty * 8 + 4];
            *(float4*)&kv[0] = *(float4*)&Kst[d * 64 + tx * 4];
#pragma unroll
            for (int r = 0; r < 8; r++)
#pragma unroll
                for (int c = 0; c < 4; c++)
                    s[r][c] = fmaf(qv[r], kv[c], s[r][c]);
        }

#pragma unroll
        for (int r = 0; r < 8; r++) {
            float mx = fmaxf(fmaxf(s[r][0], s[r][1]), fmaxf(s[r][2], s[r][3]));
#pragma unroll
            for (int off = 1; off < 16; off <<= 1)
                mx = fmaxf(mx, __shfl_xor_sync(0xffffffffu, mx, off));
            float mn = fmaxf(mrow[r], mx);
            float alpha = __expf(mrow[r] - mn);
            mrow[r] = mn;
            float p0 = __expf(s[r][0] - mn);
            float p1 = __expf(s[r][1] - mn);
            float p2 = __expf(s[r][2] - mn);
            float p3 = __expf(s[r][3] - mn);
            float rs = (p0 + p1) + (p2 + p3);
#pragma unroll
            for (int off = 1; off < 16; off <<= 1)
                rs += __shfl_xor_sync(0xffffffffu, rs, off);
            lrow[r] = lrow[r] * alpha + rs;
            o[r][0] *= alpha; o[r][1] *= alpha; o[r][2] *= alpha; o[r][3] *= alpha;
            *(float4*)&Ps[(ty * 8 + r) * 68 + tx * 4] = make_float4(p0, p1, p2, p3);
        }
        __syncthreads();

#pragma unroll
        for (int n4 = 0; n4 < 16; n4++) {
            float p[8][4], v4[4][4];
#pragma unroll
            for (int r = 0; r < 8; r++)
                *(float4*)&p[r][0] = *(float4*)&Ps[(ty * 8 + r) * 68 + n4 * 4];
#pragma unroll
            for (int i = 0; i < 4; i++)
                *(float4*)&v4[i][0] = *(float4*)&Vs[(n4 * 4 + i) * 64 + tx * 4];
#pragma unroll
            for (int r = 0; r < 8; r++)
#pragma unroll
                for (int i = 0; i < 4; i++)
#pragma unroll
                    for (int c = 0; c < 4; c++)
                        o[r][c] = fmaf(p[r][i], v4[i][c], o[r][c]);
        }
        __syncthreads();
    }

#pragma unroll
    for (int r = 0; r < 8; r++) {
        float inv = 1.0f / lrow[r];
        int sidx = q0 + ty * 8 + r;
        float* op = O + (size_t)b * SEQ * D_MODEL + (size_t)sidx * D_MODEL
                      + h * HEAD_DIM + tx * 4;
        *(float4*)op = make_float4(o[r][0] * inv, o[r][1] * inv,
                                   o[r][2] * inv, o[r][3] * inv);
    }
}

// ---------------------------------------------------------------------------
// Launch
// ---------------------------------------------------------------------------
extern "C" void kernel_launch(void* const* d_in, const int* in_sizes, int n_in,
                              void* d_out, int out_size)
{
    const float* x  = (const float*)d_in[0];
    const float* Wq = (const float*)d_in[1];
    const float* Wk = (const float*)d_in[2];
    const float* Wv = (const float*)d_in[3];
    const float* Wo = (const float*)d_in[4];
    float* out = (float*)d_out;

    float *Qp, *Kp, *Vp, *Cp;
    __nv_bfloat16 *xhi, *xlo, *wthi, *wtlo;
    cudaGetSymbolAddress((void**)&Qp, g_Q);
    cudaGetSymbolAddress((void**)&Kp, g_K);
    cudaGetSymbolAddress((void**)&Vp, g_V);
    cudaGetSymbolAddress((void**)&Cp, g_C);
    cudaGetSymbolAddress((void**)&xhi, g_xhi);
    cudaGetSymbolAddress((void**)&xlo, g_xlo);
    cudaGetSymbolAddress((void**)&wthi, g_wthi);
    cudaGetSymbolAddress((void**)&wtlo, g_wtlo);

    cudaFuncSetAttribute(attn128, cudaFuncAttributeMaxDynamicSharedMemorySize, ATTN_SMEM_BYTES);
    cudaFuncSetAttribute(gemm_mma_bf16x3, cudaFuncAttributeMaxDynamicSharedMemorySize, GEMM_SMEM);

    const size_t WSLOT = (size_t)D_MODEL * D_MODEL;
    dim3 tgrid(32, 32), tblk(32, 8);
    k_wsplit<<<tgrid, tblk>>>(Wq, wthi + 0 * WSLOT, wtlo + 0 * WSLOT);
    k_wsplit<<<tgrid, tblk>>>(Wk, wthi + 1 * WSLOT, wtlo + 1 * WSLOT);
    k_wsplit<<<tgrid, tblk>>>(Wv, wthi + 2 * WSLOT, wtlo + 2 * WSLOT);
    k_wsplit<<<tgrid, tblk>>>(Wo, wthi + 3 * WSLOT, wtlo + 3 * WSLOT);

    const int n4 = M_TOK * D_MODEL / 4;
    k_split<<<n4 / 256, 256>>>((const float4*)x, (uint2*)xhi, (uint2*)xlo, n4);

    dim3 gg(D_MODEL / 128, M_TOK / 128);   // (8, 256)
    gemm_mma_bf16x3<<<gg, 256, GEMM_SMEM>>>(xhi, xlo, wthi + 0 * WSLOT, wtlo + 0 * WSLOT, Qp,
                                            M_TOK, D_MODEL, D_MODEL);
    gemm_mma_bf16x3<<<gg, 256, GEMM_SMEM>>>(xhi, xlo, wthi + 1 * WSLOT, wtlo + 1 * WSLOT, Kp,
                                            M_TOK, D_MODEL, D_MODEL);
    gemm_mma_bf16x3<<<gg, 256, GEMM_SMEM>>>(xhi, xlo, wthi + 2 * WSLOT, wtlo + 2 * WSLOT, Vp,
                                            M_TOK, D_MODEL, D_MODEL);

    dim3 gAttn(SEQ / 128, BATCH * N_HEADS);
    attn128<<<gAttn, 256, ATTN_SMEM_BYTES>>>(Qp, Kp, Vp, Cp);

    k_split<<<n4 / 256, 256>>>((const float4*)Cp, (uint2*)xhi, (uint2*)xlo, n4);
    gemm_mma_bf16x3<<<gg, 256, GEMM_SMEM>>>(xhi, xlo, wthi + 3 * WSLOT, wtlo + 3 * WSLOT, out,
                                            M_TOK, D_MODEL, D_MODEL);
}

// round 4
// speedup vs baseline: 2.0675x; 1.3558x over previous
#include <cuda_runtime.h>
#include <cuda_bf16.h>
#include <math_constants.h>
#include <cstdint>

#define D_MODEL 1024
#define N_HEADS 16
#define HEAD_DIM 64
#define SEQ 1024
#define BATCH 32
#define M_TOK (BATCH * SEQ)   // 32768 tokens

// ---------------------------------------------------------------------------
// Scratch (alloc-free rule: __device__ globals).
// ---------------------------------------------------------------------------
__device__ __nv_bfloat16 g_xhi[(size_t)M_TOK * D_MODEL];
__device__ __nv_bfloat16 g_xlo[(size_t)M_TOK * D_MODEL];
__device__ __nv_bfloat16 g_wthi[(size_t)4 * D_MODEL * D_MODEL];
__device__ __nv_bfloat16 g_wtlo[(size_t)4 * D_MODEL * D_MODEL];
__device__ __nv_bfloat16 g_qh[(size_t)M_TOK * D_MODEL];
__device__ __nv_bfloat16 g_ql[(size_t)M_TOK * D_MODEL];
__device__ __nv_bfloat16 g_kh[(size_t)M_TOK * D_MODEL];
__device__ __nv_bfloat16 g_kl[(size_t)M_TOK * D_MODEL];
__device__ __nv_bfloat16 g_vh[(size_t)M_TOK * D_MODEL];
__device__ __nv_bfloat16 g_vl[(size_t)M_TOK * D_MODEL];
__device__ __nv_bfloat16 g_ch[(size_t)M_TOK * D_MODEL];
__device__ __nv_bfloat16 g_cl[(size_t)M_TOK * D_MODEL];

// ---------------------------------------------------------------------------
// PTX helpers — plain compute_103-legal only (mma.sync / ldmatrix / cp.async).
// ---------------------------------------------------------------------------
__device__ __forceinline__ uint32_t smem_to_u32(const void* p) {
    uint32_t a;
    asm("{ .reg .u64 t; cvta.to.shared.u64 t, %1; cvt.u32.u64 %0, t; }" : "=r"(a) : "l"(p));
    return a;
}

#define CP_ASYNC16(sa, gp) \
    asm volatile("cp.async.cg.shared.global [%0], [%1], 16;" :: "r"(sa), "l"(gp))
#define CP_COMMIT() asm volatile("cp.async.commit_group;" ::: "memory")
#define CP_WAIT1()  asm volatile("cp.async.wait_group 1;" ::: "memory")
#define CP_WAIT0()  asm volatile("cp.async.wait_group 0;" ::: "memory")

#define LDSM_X4(r, a) \
    asm volatile("ldmatrix.sync.aligned.m8n8.x4.shared.b16 {%0,%1,%2,%3}, [%4];" \
        : "=r"((r)[0]), "=r"((r)[1]), "=r"((r)[2]), "=r"((r)[3]) : "r"(a))

#define MMA16816(c, a, b0v, b1v) \
    asm volatile("mma.sync.aligned.m16n8k16.row.col.f32.bf16.bf16.f32 " \
        "{%0,%1,%2,%3}, {%4,%5,%6,%7}, {%8,%9}, {%0,%1,%2,%3};" \
        : "+f"((c)[0]), "+f"((c)[1]), "+f"((c)[2]), "+f"((c)[3]) \
        : "r"((a)[0]), "r"((a)[1]), "r"((a)[2]), "r"((a)[3]), "r"(b0v), "r"(b1v))

__device__ __forceinline__ uint32_t pack_bf16_hi(float a, float b) {
    __nv_bfloat162 t;
    t.x = __float2bfloat16_rn(a);
    t.y = __float2bfloat16_rn(b);
    return *(uint32_t*)&t;
}
__device__ __forceinline__ uint32_t pack_bf16_lo(float a, float b) {
    __nv_bfloat16 ha = __float2bfloat16_rn(a), hb = __float2bfloat16_rn(b);
    __nv_bfloat162 t;
    t.x = __float2bfloat16_rn(a - __bfloat162float(ha));
    t.y = __float2bfloat16_rn(b - __bfloat162float(hb));
    return *(uint32_t*)&t;
}

// ---------------------------------------------------------------------------
// GEMM: C[M,N] = A[M,K] * B[N,K]^T, bf16x3 via mma.sync. Block 128x128,
// 8 warps (2x4), warp tile 64x32, K-chunk 32, double-buffered cp.async.
// bfmode=0: fp32 out. bfmode=1: bf16 hi/lo split out (scaled).
// ---------------------------------------------------------------------------
#define PADB 80
#define STAGE_A (128 * PADB)
#define STAGE_BYTES (4 * STAGE_A)
#define GEMM_SMEM (2 * STAGE_BYTES)       // 81920 B

__global__ __launch_bounds__(256, 1)
void gemm_mma_bf16x3(const __nv_bfloat16* __restrict__ Ahi, const __nv_bfloat16* __restrict__ Alo,
                     const __nv_bfloat16* __restrict__ Bhi, const __nv_bfloat16* __restrict__ Blo,
                     float* __restrict__ Cf,
                     __nv_bfloat16* __restrict__ Ohi, __nv_bfloat16* __restrict__ Olo,
                     float scale, int bfmode, int M, int N, int K)
{
    extern __shared__ char smc[];
    const uint32_t sbase = smem_to_u32(smc);
    const int tid = threadIdx.x;
    const int lane = tid & 31, wid = tid >> 5;
    const int wm = wid >> 2, wn = wid & 3;
    const int m0 = blockIdx.y * 128, n0 = blockIdx.x * 128;

    float acc[4][4][4];
#pragma unroll
    for (int i = 0; i < 4; i++)
#pragma unroll
        for (int j = 0; j < 4; j++)
#pragma unroll
            for (int r = 0; r < 4; r++) acc[i][j][r] = 0.f;

    const uint32_t aoff = (uint32_t)((wm * 64 + (lane & 15)) * PADB + ((lane >> 4) & 1) * 16);
    const uint32_t boff = (uint32_t)((wn * 32 + (lane & 7) + ((lane >> 4) & 1) * 8) * PADB
                                     + ((lane >> 3) & 1) * 16);

    auto load_stage = [&](int ch, int st) {
        const uint32_t sb = sbase + st * STAGE_BYTES;
        const size_t k0 = (size_t)ch * 32;
#pragma unroll
        for (int i = 0; i < 2; i++) {
            int s = tid + 256 * i;
            int row = s >> 2, c = s & 3;
            uint32_t so = (uint32_t)(row * PADB + c * 16);
            size_t ga = ((size_t)(m0 + row) * K + k0) * 2 + c * 16;
            size_t gb = ((size_t)(n0 + row) * K + k0) * 2 + c * 16;
            CP_ASYNC16(sb + so,               (const char*)Ahi + ga);
            CP_ASYNC16(sb + STAGE_A + so,     (const char*)Alo + ga);
            CP_ASYNC16(sb + 2 * STAGE_A + so, (const char*)Bhi + gb);
            CP_ASYNC16(sb + 3 * STAGE_A + so, (const char*)Blo + gb);
        }
        CP_COMMIT();
    };

    const int NC = K / 32;
    load_stage(0, 0);

#pragma unroll 1
    for (int ch = 0; ch < NC; ch++) {
        const int st = ch & 1;
        if (ch + 1 < NC) { load_stage(ch + 1, st ^ 1); CP_WAIT1(); }
        else             { CP_WAIT0(); }
        __syncthreads();

        const uint32_t sb = sbase + st * STAGE_BYTES;
#pragma unroll
        for (int ks = 0; ks < 2; ks++) {
            const uint32_t kb = ks * 32;
            uint32_t ah[4][4], al[4][4], bh[2][4], bl[2][4];
#pragma unroll
            for (int i = 0; i < 4; i++) {
                LDSM_X4(ah[i], sb + aoff + i * (16 * PADB) + kb);
                LDSM_X4(al[i], sb + STAGE_A + aoff + i * (16 * PADB) + kb);
            }
#pragma unroll
            for (int j = 0; j < 2; j++) {
                LDSM_X4(bh[j], sb + 2 * STAGE_A + boff + j * (16 * PADB) + kb);
                LDSM_X4(bl[j], sb + 3 * STAGE_A + boff + j * (16 * PADB) + kb);
            }
#pragma unroll
            for (int i = 0; i < 4; i++)
#pragma unroll
                for (int j8 = 0; j8 < 4; j8++) {
                    const int jj = j8 >> 1, h = (j8 & 1) * 2;
                    MMA16816(acc[i][j8], ah[i], bh[jj][h], bh[jj][h + 1]);
                    MMA16816(acc[i][j8], al[i], bh[jj][h], bh[jj][h + 1]);
                    MMA16816(acc[i][j8], ah[i], bl[jj][h], bl[jj][h + 1]);
                }
        }
        __syncthreads();
    }

    const int r = lane >> 2, cl = (lane & 3) * 2;
    if (!bfmode) {
#pragma unroll
        for (int i = 0; i < 4; i++)
#pragma unroll
            for (int j8 = 0; j8 < 4; j8++) {
                int row = m0 + wm * 64 + i * 16 + r;
                int col = n0 + wn * 32 + j8 * 8 + cl;
                *(float2*)(Cf + (size_t)row * N + col) =
                    make_float2(acc[i][j8][0], acc[i][j8][1]);
                *(float2*)(Cf + (size_t)(row + 8) * N + col) =
                    make_float2(acc[i][j8][2], acc[i][j8][3]);
            }
    } else {
#pragma unroll
        for (int i = 0; i < 4; i++)
#pragma unroll
            for (int j8 = 0; j8 < 4; j8++) {
                int row = m0 + wm * 64 + i * 16 + r;
                int col = n0 + wn * 32 + j8 * 8 + cl;
                float v0 = acc[i][j8][0] * scale, v1 = acc[i][j8][1] * scale;
                float v2 = acc[i][j8][2] * scale, v3 = acc[i][j8][3] * scale;
                size_t i0 = (size_t)row * N + col;
                size_t i1 = (size_t)(row + 8) * N + col;
                *(uint32_t*)(Ohi + i0) = pack_bf16_hi(v0, v1);
                *(uint32_t*)(Olo + i0) = pack_bf16_lo(v0, v1);
                *(uint32_t*)(Ohi + i1) = pack_bf16_hi(v2, v3);
                *(uint32_t*)(Olo + i1) = pack_bf16_lo(v2, v3);
            }
    }
}

// ---------------------------------------------------------------------------
// Split fp32 -> (hi, lo) bf16, elementwise.
// ---------------------------------------------------------------------------
__global__ void k_split(const float4* __restrict__ in, uint2* __restrict__ hi,
                        uint2* __restrict__ lo, int n4)
{
    int i = blockIdx.x * blockDim.x + threadIdx.x;
    if (i >= n4) return;
    float4 v = in[i];
    float f[4] = {v.x, v.y, v.z, v.w};
    __nv_bfloat16 h[4], l[4];
#pragma unroll
    for (int j = 0; j < 4; j++) {
        h[j] = __float2bfloat16_rn(f[j]);
        l[j] = __float2bfloat16_rn(f[j] - __bfloat162float(h[j]));
    }
    hi[i] = *(uint2*)h;
    lo[i] = *(uint2*)l;
}

// Transpose + split weights: W[K,N] fp32 -> Wt_hi/lo[N,K] bf16.
__global__ void k_wsplit(const float* __restrict__ W, __nv_bfloat16* __restrict__ Th,
                         __nv_bfloat16* __restrict__ Tl)
{
    __shared__ float t[32][33];
    int k0 = blockIdx.x * 32, n0 = blockIdx.y * 32;
    int tx = threadIdx.x, ty = threadIdx.y;  // 32 x 8
#pragma unroll
    for (int i = 0; i < 4; i++)
        t[ty + 8 * i][tx] = W[(size_t)(k0 + ty + 8 * i) * D_MODEL + n0 + tx];
    __syncthreads();
#pragma unroll
    for (int i = 0; i < 4; i++) {
        float v = t[tx][ty + 8 * i];
        __nv_bfloat16 h = __float2bfloat16_rn(v);
        __nv_bfloat16 l = __float2bfloat16_rn(v - __bfloat162float(h));
        size_t o = (size_t)(n0 + ty + 8 * i) * D_MODEL + k0 + tx;
        Th[o] = h;
        Tl[o] = l;
    }
}

// ---------------------------------------------------------------------------
// Flash attention on tensor cores (bf16x3 QK^T and PV, fp32 softmax state).
// Block: (q-tile 128, b*h). 8 warps; warp w owns q rows [w*16, w*16+16).
// Smem: Q hi/lo (128x64), double-buffered K/V tiles (64 keys), V^T work buf.
// ---------------------------------------------------------------------------
#define ATT_PAD 144
#define SMQ_H 0
#define SMQ_L (128 * ATT_PAD)                 // 18432
#define SM_STAGE0 (2 * 128 * ATT_PAD)         // 36864
#define ATT_STG (4 * 64 * ATT_PAD)            // 36864 per stage: Kh,Kl,Vh,Vl
#define ATT_KL 9216
#define ATT_VH 18432
#define ATT_VL 27648
#define SM_VT (SM_STAGE0 + 2 * ATT_STG)       // 110592: VtWh, VtWl
#define ATT_SMEM (SM_VT + 2 * 64 * ATT_PAD)   // 129024

__global__ __launch_bounds__(256, 1)
void attn_mma(const __nv_bfloat16* __restrict__ Qhg, const __nv_bfloat16* __restrict__ Qlg,
              const __nv_bfloat16* __restrict__ Khg, const __nv_bfloat16* __restrict__ Klg,
              const __nv_bfloat16* __restrict__ Vhg, const __nv_bfloat16* __restrict__ Vlg,
              __nv_bfloat16* __restrict__ Chg, __nv_bfloat16* __restrict__ Clg)
{
    extern __shared__ char smc[];
    const uint32_t sb = smem_to_u32(smc);
    const int tid = threadIdx.x, lane = tid & 31, w = tid >> 5;
    const int b = blockIdx.y >> 4, h = blockIdx.y & 15;
    const int q0 = blockIdx.x * 128;
    const size_t rowB = (size_t)D_MODEL * 2;   // global row stride (bytes)

    const char* Qh = (const char*)Qhg + ((size_t)(b * SEQ + q0) * D_MODEL + h * 64) * 2;
    const char* Ql = (const char*)Qlg + ((size_t)(b * SEQ + q0) * D_MODEL + h * 64) * 2;
    const char* Kh = (const char*)Khg + ((size_t)(b * SEQ) * D_MODEL + h * 64) * 2;
    const char* Kl = (const char*)Klg + ((size_t)(b * SEQ) * D_MODEL + h * 64) * 2;
    const char* Vh = (const char*)Vhg + ((size_t)(b * SEQ) * D_MODEL + h * 64) * 2;
    const char* Vl = (const char*)Vlg + ((size_t)(b * SEQ) * D_MODEL + h * 64) * 2;

    // Q tile loads (group 0)
    for (int i = tid; i < 1024; i += 256) {
        int r = i >> 3, c = i & 7;
        uint32_t so = (uint32_t)(r * ATT_PAD + c * 16);
        CP_ASYNC16(sb + SMQ_H + so, Qh + (size_t)r * rowB + c * 16);
        CP_ASYNC16(sb + SMQ_L + so, Ql + (size_t)r * rowB + c * 16);
    }
    CP_COMMIT();

    auto load_kv = [&](int tile, int st) {
        const uint32_t stB = sb + SM_STAGE0 + st * ATT_STG;
        const size_t n0b = (size_t)(tile * 64) * rowB;
        for (int i = tid; i < 512; i += 256) {
            int r = i >> 3, c = i & 7;
            size_t go = n0b + (size_t)r * rowB + c * 16;
            uint32_t so = (uint32_t)(r * ATT_PAD + c * 16);
            CP_ASYNC16(stB + so,          Kh + go);
            CP_ASYNC16(stB + ATT_KL + so, Kl + go);
            CP_ASYNC16(stB + ATT_VH + so, Vh + go);
            CP_ASYNC16(stB + ATT_VL + so, Vl + go);
        }
        CP_COMMIT();
    };

    load_kv(0, 0);
    CP_WAIT1();          // Q group done
    __syncthreads();

    // Q A-fragments (loop-invariant)
    uint32_t qh[4][4], ql[4][4];
    {
        const uint32_t ao = (uint32_t)((w * 16 + (lane & 15)) * ATT_PAD + ((lane >> 4) & 1) * 16);
#pragma unroll
        for (int t = 0; t < 4; t++) {
            LDSM_X4(qh[t], sb + SMQ_H + ao + t * 32);
            LDSM_X4(ql[t], sb + SMQ_L + ao + t * 32);
        }
    }

    float o[8][4];
#pragma unroll
    for (int j = 0; j < 8; j++)
#pragma unroll
        for (int r = 0; r < 4; r++) o[j][r] = 0.f;
    float m0 = -CUDART_INF_F, m1 = -CUDART_INF_F, l0 = 0.f, l1 = 0.f;

    const uint32_t bo = (uint32_t)(((lane & 7) + ((lane >> 4) & 1) * 8) * ATT_PAD
                                   + ((lane >> 3) & 1) * 16);

#pragma unroll 1
    for (int tile = 0; tile < 16; tile++) {
        const int st = tile & 1;
        if (tile + 1 < 16) { load_kv(tile + 1, st ^ 1); CP_WAIT1(); }
        else               { CP_WAIT0(); }
        __syncthreads();

        // Transpose V stage -> VtW (d-major, key contig)
        const uint32_t stB = SM_STAGE0 + st * ATT_STG;
        for (int i = tid; i < 2048; i += 256) {
            int r = i >> 5, c2 = i & 31;
            uint32_t vh2 = *(const uint32_t*)(smc + stB + ATT_VH + r * ATT_PAD + c2 * 4);
            uint32_t vl2 = *(const uint32_t*)(smc + stB + ATT_VL + r * ATT_PAD + c2 * 4);
            const __nv_bfloat16* ph = (const __nv_bfloat16*)&vh2;
            const __nv_bfloat16* pl = (const __nv_bfloat16*)&vl2;
            *(__nv_bfloat16*)(smc + SM_VT + (2 * c2) * ATT_PAD + r * 2)     = ph[0];
            *(__nv_bfloat16*)(smc + SM_VT + (2 * c2 + 1) * ATT_PAD + r * 2) = ph[1];
            *(__nv_bfloat16*)(smc + SM_VT + ATT_KL + (2 * c2) * ATT_PAD + r * 2)     = pl[0];
            *(__nv_bfloat16*)(smc + SM_VT + ATT_KL + (2 * c2 + 1) * ATT_PAD + r * 2) = pl[1];
        }
        __syncthreads();

        // S = Q K^T   (128x64 tile; this warp: 16x64)
        float s[8][4];
#pragma unroll
        for (int j = 0; j < 8; j++)
#pragma unroll
            for (int r = 0; r < 4; r++) s[j][r] = 0.f;

        const uint32_t sbK = sb + stB;
#pragma unroll
        for (int t = 0; t < 4; t++)
#pragma unroll
            for (int g = 0; g < 4; g++) {
                uint32_t ro = bo + (uint32_t)(g * 16 * ATT_PAD) + t * 32;
                uint32_t kh4[4], kl4[4];
                LDSM_X4(kh4, sbK + ro);
                LDSM_X4(kl4, sbK + ATT_KL + ro);
#pragma unroll
                for (int hf = 0; hf < 2; hf++) {
                    MMA16816(s[g * 2 + hf], qh[t], kh4[hf * 2], kh4[hf * 2 + 1]);
                    MMA16816(s[g * 2 + hf], ql[t], kh4[hf * 2], kh4[hf * 2 + 1]);
                    MMA16816(s[g * 2 + hf], qh[t], kl4[hf * 2], kl4[hf * 2 + 1]);
                }
            }

        // Online softmax (rows: lane>>2 and +8; 4 lanes per row group)
        float mx0 = -CUDART_INF_F, mx1 = -CUDART_INF_F;
#pragma unroll
        for (int j = 0; j < 8; j++) {
            mx0 = fmaxf(mx0, fmaxf(s[j][0], s[j][1]));
            mx1 = fmaxf(mx1, fmaxf(s[j][2], s[j][3]));
        }
        mx0 = fmaxf(mx0, __shfl_xor_sync(0xffffffffu, mx0, 1));
        mx0 = fmaxf(mx0, __shfl_xor_sync(0xffffffffu, mx0, 2));
        mx1 = fmaxf(mx1, __shfl_xor_sync(0xffffffffu, mx1, 1));
        mx1 = fmaxf(mx1, __shfl_xor_sync(0xffffffffu, mx1, 2));
        float mn0 = fmaxf(m0, mx0), mn1 = fmaxf(m1, mx1);
        float a0 = __expf(m0 - mn0), a1 = __expf(m1 - mn1);
        m0 = mn0; m1 = mn1;
        float rs0 = 0.f, rs1 = 0.f;
#pragma unroll
        for (int j = 0; j < 8; j++) {
            s[j][0] = __expf(s[j][0] - mn0);
            s[j][1] = __expf(s[j][1] - mn0);
            s[j][2] = __expf(s[j][2] - mn1);
            s[j][3] = __expf(s[j][3] - mn1);
            rs0 += s[j][0] + s[j][1];
            rs1 += s[j][2] + s[j][3];
        }
        rs0 += __shfl_xor_sync(0xffffffffu, rs0, 1);
        rs0 += __shfl_xor_sync(0xffffffffu, rs0, 2);
        rs1 += __shfl_xor_sync(0xffffffffu, rs1, 1);
        rs1 += __shfl_xor_sync(0xffffffffu, rs1, 2);
        l0 = l0 * a0 + rs0;
        l1 = l1 * a1 + rs1;
#pragma unroll
        for (int j = 0; j < 8; j++) {
            o[j][0] *= a0; o[j][1] *= a0;
            o[j][2] *= a1; o[j][3] *= a1;
        }

        // O += P V  (P frags built in registers from S frags)
#pragma unroll
        for (int t = 0; t < 4; t++) {
            uint32_t pah[4], pal[4];
            pah[0] = pack_bf16_hi(s[2 * t][0], s[2 * t][1]);
            pal[0] = pack_bf16_lo(s[2 * t][0], s[2 * t][1]);
            pah[1] = pack_bf16_hi(s[2 * t][2], s[2 * t][3]);
            pal[1] = pack_bf16_lo(s[2 * t][2], s[2 * t][3]);
            pah[2] = pack_bf16_hi(s[2 * t + 1][0], s[2 * t + 1][1]);
            pal[2] = pack_bf16_lo(s[2 * t + 1][0], s[2 * t + 1][1]);
            pah[3] = pack_bf16_hi(s[2 * t + 1][2], s[2 * t + 1][3]);
            pal[3] = pack_bf16_lo(s[2 * t + 1][2], s[2 * t + 1][3]);
#pragma unroll
            for (int g = 0; g < 4; g++) {
                uint32_t ro = bo + (uint32_t)(g * 16 * ATT_PAD) + t * 32;
                uint32_t vh4[4], vl4[4];
                LDSM_X4(vh4, sb + SM_VT + ro);
                LDSM_X4(vl4, sb + SM_VT + ATT_KL + ro);
#pragma unroll
                for (int hf = 0; hf < 2; hf++) {
                    MMA16816(o[g * 2 + hf], pah, vh4[hf * 2], vh4[hf * 2 + 1]);
                    MMA16816(o[g * 2 + hf], pal, vh4[hf * 2], vh4[hf * 2 + 1]);
                    MMA16816(o[g * 2 + hf], pah, vl4[hf * 2], vl4[hf * 2 + 1]);
                }
            }
        }
        __syncthreads();
    }

    // Epilogue: normalize, split hi/lo, store ctx bf16.
    const float inv0 = 1.0f / l0, inv1 = 1.0f / l1;
    const int s0 = q0 + w * 16 + (lane >> 2);
    const int cl = (lane & 3) * 2;
#pragma unroll
    for (int j8 = 0; j8 < 8; j8++) {
        int col = h * 64 + j8 * 8 + cl;
        size_t i0 = (size_t)(b * SEQ + s0) * D_MODEL + col;
        size_t i1 = (size_t)(b * SEQ + s0 + 8) * D_MODEL + col;
        float v0 = o[j8][0] * inv0, v1 = o[j8][1] * inv0;
        float v2 = o[j8][2] * inv1, v3 = o[j8][3] * inv1;
        *(uint32_t*)(Chg + i0) = pack_bf16_hi(v0, v1);
        *(uint32_t*)(Clg + i0) = pack_bf16_lo(v0, v1);
        *(uint32_t*)(Chg + i1) = pack_bf16_hi(v2, v3);
        *(uint32_t*)(Clg + i1) = pack_bf16_lo(v2, v3);
    }
}

// ---------------------------------------------------------------------------
// Launch
// ---------------------------------------------------------------------------
extern "C" void kernel_launch(void* const* d_in, const int* in_sizes, int n_in,
                              void* d_out, int out_size)
{
    const float* x  = (const float*)d_in[0];
    const float* Wq = (const float*)d_in[1];
    const float* Wk = (const float*)d_in[2];
    const float* Wv = (const float*)d_in[3];
    const float* Wo = (const float*)d_in[4];
    float* out = (float*)d_out;

    __nv_bfloat16 *xhi, *xlo, *wthi, *wtlo, *qh, *ql, *kh, *kl, *vh, *vl, *ch, *cl;
    cudaGetSymbolAddress((void**)&xhi, g_xhi);
    cudaGetSymbolAddress((void**)&xlo, g_xlo);
    cudaGetSymbolAddress((void**)&wthi, g_wthi);
    cudaGetSymbolAddress((void**)&wtlo, g_wtlo);
    cudaGetSymbolAddress((void**)&qh, g_qh);
    cudaGetSymbolAddress((void**)&ql, g_ql);
    cudaGetSymbolAddress((void**)&kh, g_kh);
    cudaGetSymbolAddress((void**)&kl, g_kl);
    cudaGetSymbolAddress((void**)&vh, g_vh);
    cudaGetSymbolAddress((void**)&vl, g_vl);
    cudaGetSymbolAddress((void**)&ch, g_ch);
    cudaGetSymbolAddress((void**)&cl, g_cl);

    cudaFuncSetAttribute(gemm_mma_bf16x3, cudaFuncAttributeMaxDynamicSharedMemorySize, GEMM_SMEM);
    cudaFuncSetAttribute(attn_mma, cudaFuncAttributeMaxDynamicSharedMemorySize, ATT_SMEM);

    const size_t WSLOT = (size_t)D_MODEL * D_MODEL;
    dim3 tgrid(32, 32), tblk(32, 8);
    k_wsplit<<<tgrid, tblk>>>(Wq, wthi + 0 * WSLOT, wtlo + 0 * WSLOT);
    k_wsplit<<<tgrid, tblk>>>(Wk, wthi + 1 * WSLOT, wtlo + 1 * WSLOT);
    k_wsplit<<<tgrid, tblk>>>(Wv, wthi + 2 * WSLOT, wtlo + 2 * WSLOT);
    k_wsplit<<<tgrid, tblk>>>(Wo, wthi + 3 * WSLOT, wtlo + 3 * WSLOT);

    const int n4 = M_TOK * D_MODEL / 4;
    k_split<<<n4 / 256, 256>>>((const float4*)x, (uint2*)xhi, (uint2*)xlo, n4);

    dim3 gg(D_MODEL / 128, M_TOK / 128);   // (8, 256)
    gemm_mma_bf16x3<<<gg, 256, GEMM_SMEM>>>(xhi, xlo, wthi + 0 * WSLOT, wtlo + 0 * WSLOT,
                                            nullptr, qh, ql, 0.125f, 1,
                                            M_TOK, D_MODEL, D_MODEL);
    gemm_mma_bf16x3<<<gg, 256, GEMM_SMEM>>>(xhi, xlo, wthi + 1 * WSLOT, wtlo + 1 * WSLOT,
                                            nullptr, kh, kl, 1.0f, 1,
                                            M_TOK, D_MODEL, D_MODEL);
    gemm_mma_bf16x3<<<gg, 256, GEMM_SMEM>>>(xhi, xlo, wthi + 2 * WSLOT, wtlo + 2 * WSLOT,
                                            nullptr, vh, vl, 1.0f, 1,
                                            M_TOK, D_MODEL, D_MODEL);

    dim3 gAttn(SEQ / 128, BATCH * N_HEADS);   // (8, 512)
    attn_mma<<<gAttn, 256, ATT_SMEM>>>(qh, ql, kh, kl, vh, vl, ch, cl);

    gemm_mma_bf16x3<<<gg, 256, GEMM_SMEM>>>(ch, cl, wthi + 3 * WSLOT, wtlo + 3 * WSLOT,
                                            out, nullptr, nullptr, 1.0f, 0,
                                            M_TOK, D_MODEL, D_MODEL);
}

// round 5
// speedup vs baseline: 2.2778x; 1.1017x over previous
#include <cuda_runtime.h>
#include <cuda_bf16.h>
#include <math_constants.h>
#include <cstdint>

#define D_MODEL 1024
#define N_HEADS 16
#define HEAD_DIM 64
#define SEQ 1024
#define BATCH 32
#define M_TOK (BATCH * SEQ)   // 32768 tokens

// ---------------------------------------------------------------------------
// Scratch (alloc-free rule: __device__ globals).
// ---------------------------------------------------------------------------
__device__ __nv_bfloat16 g_xhi[(size_t)M_TOK * D_MODEL];
__device__ __nv_bfloat16 g_xlo[(size_t)M_TOK * D_MODEL];
__device__ __nv_bfloat16 g_wthi[(size_t)4 * D_MODEL * D_MODEL];
__device__ __nv_bfloat16 g_wtlo[(size_t)4 * D_MODEL * D_MODEL];
__device__ __nv_bfloat16 g_qh[(size_t)M_TOK * D_MODEL];
__device__ __nv_bfloat16 g_ql[(size_t)M_TOK * D_MODEL];
__device__ __nv_bfloat16 g_kh[(size_t)M_TOK * D_MODEL];
__device__ __nv_bfloat16 g_kl[(size_t)M_TOK * D_MODEL];
__device__ __nv_bfloat16 g_vh[(size_t)M_TOK * D_MODEL];
__device__ __nv_bfloat16 g_vl[(size_t)M_TOK * D_MODEL];
__device__ __nv_bfloat16 g_ch[(size_t)M_TOK * D_MODEL];
__device__ __nv_bfloat16 g_cl[(size_t)M_TOK * D_MODEL];

// ---------------------------------------------------------------------------
// PTX helpers — plain compute_103-legal only (mma.sync / ldmatrix / cp.async).
// ---------------------------------------------------------------------------
__device__ __forceinline__ uint32_t smem_to_u32(const void* p) {
    uint32_t a;
    asm("{ .reg .u64 t; cvta.to.shared.u64 t, %1; cvt.u32.u64 %0, t; }" : "=r"(a) : "l"(p));
    return a;
}

#define CP_ASYNC16(sa, gp) \
    asm volatile("cp.async.cg.shared.global [%0], [%1], 16;" :: "r"(sa), "l"(gp))
#define CP_COMMIT() asm volatile("cp.async.commit_group;" ::: "memory")
#define CP_WAIT1()  asm volatile("cp.async.wait_group 1;" ::: "memory")
#define CP_WAIT0()  asm volatile("cp.async.wait_group 0;" ::: "memory")

#define LDSM_X4(r, a) \
    asm volatile("ldmatrix.sync.aligned.m8n8.x4.shared.b16 {%0,%1,%2,%3}, [%4];" \
        : "=r"((r)[0]), "=r"((r)[1]), "=r"((r)[2]), "=r"((r)[3]) : "r"(a))

#define MMA16816(c, a, b0v, b1v) \
    asm volatile("mma.sync.aligned.m16n8k16.row.col.f32.bf16.bf16.f32 " \
        "{%0,%1,%2,%3}, {%4,%5,%6,%7}, {%8,%9}, {%0,%1,%2,%3};" \
        : "+f"((c)[0]), "+f"((c)[1]), "+f"((c)[2]), "+f"((c)[3]) \
        : "r"((a)[0]), "r"((a)[1]), "r"((a)[2]), "r"((a)[3]), "r"(b0v), "r"(b1v))

__device__ __forceinline__ uint32_t pack_bf16_hi(float a, float b) {
    __nv_bfloat162 t;
    t.x = __float2bfloat16_rn(a);
    t.y = __float2bfloat16_rn(b);
    return *(uint32_t*)&t;
}
__device__ __forceinline__ uint32_t pack_bf16_lo(float a, float b) {
    __nv_bfloat16 ha = __float2bfloat16_rn(a), hb = __float2bfloat16_rn(b);
    __nv_bfloat162 t;
    t.x = __float2bfloat16_rn(a - __bfloat162float(ha));
    t.y = __float2bfloat16_rn(b - __bfloat162float(hb));
    return *(uint32_t*)&t;
}

// ---------------------------------------------------------------------------
// GEMM: C[M,N] = A[M,K] * B[N,K]^T, bf16x3 via mma.sync. Block 128x256,
// 8 warps (2x4), warp tile 64x64. K-chunk 32, double-buffered cp.async.
// bfmode=0: fp32 out. bfmode=1: bf16 hi/lo split out (scaled).
// ---------------------------------------------------------------------------
#define PADB 80
#define STG_AL 10240                     // 128*80
#define STG_BH 20480
#define STG_BL 40960                     // + 256*80
#define STAGE_BYTES 61440
#define GEMM_SMEM (2 * STAGE_BYTES)      // 122880 B

__global__ __launch_bounds__(256, 1)
void gemm_mma_bf16x3(const __nv_bfloat16* __restrict__ Ahi, const __nv_bfloat16* __restrict__ Alo,
                     const __nv_bfloat16* __restrict__ Bhi, const __nv_bfloat16* __restrict__ Blo,
                     float* __restrict__ Cf,
                     __nv_bfloat16* __restrict__ Ohi, __nv_bfloat16* __restrict__ Olo,
                     float scale, int bfmode, int M, int N, int K)
{
    extern __shared__ char smc[];
    const uint32_t sbase = smem_to_u32(smc);
    const int tid = threadIdx.x;
    const int lane = tid & 31, wid = tid >> 5;
    const int wm = wid >> 2, wn = wid & 3;           // warp grid 2(M) x 4(N)
    const int m0 = blockIdx.y * 128, n0 = blockIdx.x * 256;

    float acc[4][8][4];
#pragma unroll
    for (int i = 0; i < 4; i++)
#pragma unroll
        for (int j = 0; j < 8; j++)
#pragma unroll
            for (int r = 0; r < 4; r++) acc[i][j][r] = 0.f;

    const uint32_t aoff = (uint32_t)((wm * 64 + (lane & 15)) * PADB + ((lane >> 4) & 1) * 16);
    const uint32_t boff = (uint32_t)((wn * 64 + (lane & 7) + ((lane >> 4) & 1) * 8) * PADB
                                     + ((lane >> 3) & 1) * 16);

    auto load_stage = [&](int ch, int st) {
        const uint32_t sb = sbase + st * STAGE_BYTES;
        const size_t k0 = (size_t)ch * 32;
        // A: 128 rows x 4 x 16B, hi+lo
#pragma unroll
        for (int i = 0; i < 2; i++) {
            int s = tid + 256 * i;           // 0..511
            int row = s >> 2, c = s & 3;
            uint32_t so = (uint32_t)(row * PADB + c * 16);
            size_t ga = ((size_t)(m0 + row) * K + k0) * 2 + c * 16;
            CP_ASYNC16(sb + so,          (const char*)Ahi + ga);
            CP_ASYNC16(sb + STG_AL + so, (const char*)Alo + ga);
        }
        // B: 256 rows x 4 x 16B, hi+lo
#pragma unroll
        for (int i = 0; i < 4; i++) {
            int s = tid + 256 * i;           // 0..1023
            int row = s >> 2, c = s & 3;
            uint32_t so = (uint32_t)(row * PADB + c * 16);
            size_t gb = ((size_t)(n0 + row) * K + k0) * 2 + c * 16;
            CP_ASYNC16(sb + STG_BH + so, (const char*)Bhi + gb);
            CP_ASYNC16(sb + STG_BL + so, (const char*)Blo + gb);
        }
        CP_COMMIT();
    };

    const int NC = K / 32;
    load_stage(0, 0);

#pragma unroll 1
    for (int ch = 0; ch < NC; ch++) {
        const int st = ch & 1;
        if (ch + 1 < NC) { load_stage(ch + 1, st ^ 1); CP_WAIT1(); }
        else             { CP_WAIT0(); }
        __syncthreads();

        const uint32_t sb = sbase + st * STAGE_BYTES;
#pragma unroll
        for (int ks = 0; ks < 2; ks++) {
            const uint32_t kb = ks * 32;
            uint32_t ah[4][4], al[4][4];
#pragma unroll
            for (int i = 0; i < 4; i++) {
                LDSM_X4(ah[i], sb + aoff + i * (16 * PADB) + kb);
                LDSM_X4(al[i], sb + STG_AL + aoff + i * (16 * PADB) + kb);
            }
#pragma unroll
            for (int j = 0; j < 4; j++) {
                uint32_t bh4[4], bl4[4];
                LDSM_X4(bh4, sb + STG_BH + boff + j * (16 * PADB) + kb);
                LDSM_X4(bl4, sb + STG_BL + boff + j * (16 * PADB) + kb);
#pragma unroll
                for (int i = 0; i < 4; i++)
#pragma unroll
                    for (int hf = 0; hf < 2; hf++) {
                        MMA16816(acc[i][j * 2 + hf], ah[i], bh4[hf * 2], bh4[hf * 2 + 1]);
                        MMA16816(acc[i][j * 2 + hf], al[i], bh4[hf * 2], bh4[hf * 2 + 1]);
                        MMA16816(acc[i][j * 2 + hf], ah[i], bl4[hf * 2], bl4[hf * 2 + 1]);
                    }
            }
        }
        __syncthreads();
    }

    const int r = lane >> 2, cl = (lane & 3) * 2;
    if (!bfmode) {
#pragma unroll
        for (int i = 0; i < 4; i++)
#pragma unroll
            for (int j8 = 0; j8 < 8; j8++) {
                int row = m0 + wm * 64 + i * 16 + r;
                int col = n0 + wn * 64 + j8 * 8 + cl;
                *(float2*)(Cf + (size_t)row * N + col) =
                    make_float2(acc[i][j8][0], acc[i][j8][1]);
                *(float2*)(Cf + (size_t)(row + 8) * N + col) =
                    make_float2(acc[i][j8][2], acc[i][j8][3]);
            }
    } else {
#pragma unroll
        for (int i = 0; i < 4; i++)
#pragma unroll
            for (int j8 = 0; j8 < 8; j8++) {
                int row = m0 + wm * 64 + i * 16 + r;
                int col = n0 + wn * 64 + j8 * 8 + cl;
                float v0 = acc[i][j8][0] * scale, v1 = acc[i][j8][1] * scale;
                float v2 = acc[i][j8][2] * scale, v3 = acc[i][j8][3] * scale;
                size_t i0 = (size_t)row * N + col;
                size_t i1 = (size_t)(row + 8) * N + col;
                *(uint32_t*)(Ohi + i0) = pack_bf16_hi(v0, v1);
                *(uint32_t*)(Olo + i0) = pack_bf16_lo(v0, v1);
                *(uint32_t*)(Ohi + i1) = pack_bf16_hi(v2, v3);
                *(uint32_t*)(Olo + i1) = pack_bf16_lo(v2, v3);
            }
    }
}

// ---------------------------------------------------------------------------
// Split fp32 -> (hi, lo) bf16, elementwise.
// ---------------------------------------------------------------------------
__global__ void k_split(const float4* __restrict__ in, uint2* __restrict__ hi,
                        uint2* __restrict__ lo, int n4)
{
    int i = blockIdx.x * blockDim.x + threadIdx.x;
    if (i >= n4) return;
    float4 v = in[i];
    float f[4] = {v.x, v.y, v.z, v.w};
    __nv_bfloat16 h[4], l[4];
#pragma unroll
    for (int j = 0; j < 4; j++) {
        h[j] = __float2bfloat16_rn(f[j]);
        l[j] = __float2bfloat16_rn(f[j] - __bfloat162float(h[j]));
    }
    hi[i] = *(uint2*)h;
    lo[i] = *(uint2*)l;
}

// Transpose + split weights: W[K,N] fp32 -> Wt_hi/lo[N,K] bf16.
__global__ void k_wsplit(const float* __restrict__ W, __nv_bfloat16* __restrict__ Th,
                         __nv_bfloat16* __restrict__ Tl)
{
    __shared__ float t[32][33];
    int k0 = blockIdx.x * 32, n0 = blockIdx.y * 32;
    int tx = threadIdx.x, ty = threadIdx.y;  // 32 x 8
#pragma unroll
    for (int i = 0; i < 4; i++)
        t[ty + 8 * i][tx] = W[(size_t)(k0 + ty + 8 * i) * D_MODEL + n0 + tx];
    __syncthreads();
#pragma unroll
    for (int i = 0; i < 4; i++) {
        float v = t[tx][ty + 8 * i];
        __nv_bfloat16 h = __float2bfloat16_rn(v);
        __nv_bfloat16 l = __float2bfloat16_rn(v - __bfloat162float(h));
        size_t o = (size_t)(n0 + ty + 8 * i) * D_MODEL + k0 + tx;
        Th[o] = h;
        Tl[o] = l;
    }
}

// ---------------------------------------------------------------------------
// Flash attention on tensor cores (bf16x3 QK^T and PV, fp32 softmax state).
// ---------------------------------------------------------------------------
#define ATT_PAD 144
#define SMQ_H 0
#define SMQ_L (128 * ATT_PAD)
#define SM_STAGE0 (2 * 128 * ATT_PAD)
#define ATT_STG (4 * 64 * ATT_PAD)
#define ATT_KL 9216
#define ATT_VH 18432
#define ATT_VL 27648
#define SM_VT (SM_STAGE0 + 2 * ATT_STG)
#define ATT_SMEM (SM_VT + 2 * 64 * ATT_PAD)   // 129024

__global__ __launch_bounds__(256, 1)
void attn_mma(const __nv_bfloat16* __restrict__ Qhg, const __nv_bfloat16* __restrict__ Qlg,
              const __nv_bfloat16* __restrict__ Khg, const __nv_bfloat16* __restrict__ Klg,
              const __nv_bfloat16* __restrict__ Vhg, const __nv_bfloat16* __restrict__ Vlg,
              __nv_bfloat16* __restrict__ Chg, __nv_bfloat16* __restrict__ Clg)
{
    extern __shared__ char smc[];
    const uint32_t sb = smem_to_u32(smc);
    const int tid = threadIdx.x, lane = tid & 31, w = tid >> 5;
    const int b = blockIdx.y >> 4, h = blockIdx.y & 15;
    const int q0 = blockIdx.x * 128;
    const size_t rowB = (size_t)D_MODEL * 2;

    const char* Qh = (const char*)Qhg + ((size_t)(b * SEQ + q0) * D_MODEL + h * 64) * 2;
    const char* Ql = (const char*)Qlg + ((size_t)(b * SEQ + q0) * D_MODEL + h * 64) * 2;
    const char* Kh = (const char*)Khg + ((size_t)(b * SEQ) * D_MODEL + h * 64) * 2;
    const char* Kl = (const char*)Klg + ((size_t)(b * SEQ) * D_MODEL + h * 64) * 2;
    const char* Vh = (const char*)Vhg + ((size_t)(b * SEQ) * D_MODEL + h * 64) * 2;
    const char* Vl = (const char*)Vlg + ((size_t)(b * SEQ) * D_MODEL + h * 64) * 2;

    for (int i = tid; i < 1024; i += 256) {
        int r = i >> 3, c = i & 7;
        uint32_t so = (uint32_t)(r * ATT_PAD + c * 16);
        CP_ASYNC16(sb + SMQ_H + so, Qh + (size_t)r * rowB + c * 16);
        CP_ASYNC16(sb + SMQ_L + so, Ql + (size_t)r * rowB + c * 16);
    }
    CP_COMMIT();

    auto load_kv = [&](int tile, int st) {
        const uint32_t stB = sb + SM_STAGE0 + st * ATT_STG;
        const size_t n0b = (size_t)(tile * 64) * rowB;
        for (int i = tid; i < 512; i += 256) {
            int r = i >> 3, c = i & 7;
            size_t go = n0b + (size_t)r * rowB + c * 16;
            uint32_t so = (uint32_t)(r * ATT_PAD + c * 16);
            CP_ASYNC16(stB + so,          Kh + go);
            CP_ASYNC16(stB + ATT_KL + so, Kl + go);
            CP_ASYNC16(stB + ATT_VH + so, Vh + go);
            CP_ASYNC16(stB + ATT_VL + so, Vl + go);
        }
        CP_COMMIT();
    };

    load_kv(0, 0);
    CP_WAIT1();
    __syncthreads();

    uint32_t qh[4][4], ql[4][4];
    {
        const uint32_t ao = (uint32_t)((w * 16 + (lane & 15)) * ATT_PAD + ((lane >> 4) & 1) * 16);
#pragma unroll
        for (int t = 0; t < 4; t++) {
            LDSM_X4(qh[t], sb + SMQ_H + ao + t * 32);
            LDSM_X4(ql[t], sb + SMQ_L + ao + t * 32);
        }
    }

    float o[8][4];
#pragma unroll
    for (int j = 0; j < 8; j++)
#pragma unroll
        for (int r = 0; r < 4; r++) o[j][r] = 0.f;
    float m0 = -CUDART_INF_F, m1 = -CUDART_INF_F, l0 = 0.f, l1 = 0.f;

    const uint32_t bo = (uint32_t)(((lane & 7) + ((lane >> 4) & 1) * 8) * ATT_PAD
                                   + ((lane >> 3) & 1) * 16);

#pragma unroll 1
    for (int tile = 0; tile < 16; tile++) {
        const int st = tile & 1;
        if (tile + 1 < 16) { load_kv(tile + 1, st ^ 1); CP_WAIT1(); }
        else               { CP_WAIT0(); }
        __syncthreads();

        const uint32_t stB = SM_STAGE0 + st * ATT_STG;
        for (int i = tid; i < 2048; i += 256) {
            int r = i >> 5, c2 = i & 31;
            uint32_t vh2 = *(const uint32_t*)(smc + stB + ATT_VH + r * ATT_PAD + c2 * 4);
            uint32_t vl2 = *(const uint32_t*)(smc + stB + ATT_VL + r * ATT_PAD + c2 * 4);
            const __nv_bfloat16* ph = (const __nv_bfloat16*)&vh2;
            const __nv_bfloat16* pl = (const __nv_bfloat16*)&vl2;
            *(__nv_bfloat16*)(smc + SM_VT + (2 * c2) * ATT_PAD + r * 2)     = ph[0];
            *(__nv_bfloat16*)(smc + SM_VT + (2 * c2 + 1) * ATT_PAD + r * 2) = ph[1];
            *(__nv_bfloat16*)(smc + SM_VT + ATT_KL + (2 * c2) * ATT_PAD + r * 2)     = pl[0];
            *(__nv_bfloat16*)(smc + SM_VT + ATT_KL + (2 * c2 + 1) * ATT_PAD + r * 2) = pl[1];
        }
        __syncthreads();

        float s[8][4];
#pragma unroll
        for (int j = 0; j < 8; j++)
#pragma unroll
            for (int r = 0; r < 4; r++) s[j][r] = 0.f;

        const uint32_t sbK = sb + stB;
#pragma unroll
        for (int t = 0; t < 4; t++)
#pragma unroll
            for (int g = 0; g < 4; g++) {
                uint32_t ro = bo + (uint32_t)(g * 16 * ATT_PAD) + t * 32;
                uint32_t kh4[4], kl4[4];
                LDSM_X4(kh4, sbK + ro);
                LDSM_X4(kl4, sbK + ATT_KL + ro);
#pragma unroll
                for (int hf = 0; hf < 2; hf++) {
                    MMA16816(s[g * 2 + hf], qh[t], kh4[hf * 2], kh4[hf * 2 + 1]);
                    MMA16816(s[g * 2 + hf], ql[t], kh4[hf * 2], kh4[hf * 2 + 1]);
                    MMA16816(s[g * 2 + hf], qh[t], kl4[hf * 2], kl4[hf * 2 + 1]);
                }
            }

        float mx0 = -CUDART_INF_F, mx1 = -CUDART_INF_F;
#pragma unroll
        for (int j = 0; j < 8; j++) {
            mx0 = fmaxf(mx0, fmaxf(s[j][0], s[j][1]));
            mx1 = fmaxf(mx1, fmaxf(s[j][2], s[j][3]));
        }
        mx0 = fmaxf(mx0, __shfl_xor_sync(0xffffffffu, mx0, 1));
        mx0 = fmaxf(mx0, __shfl_xor_sync(0xffffffffu, mx0, 2));
        mx1 = fmaxf(mx1, __shfl_xor_sync(0xffffffffu, mx1, 1));
        mx1 = fmaxf(mx1, __shfl_xor_sync(0xffffffffu, mx1, 2));
        float mn0 = fmaxf(m0, mx0), mn1 = fmaxf(m1, mx1);
        float a0 = __expf(m0 - mn0), a1 = __expf(m1 - mn1);
        m0 = mn0; m1 = mn1;
        float rs0 = 0.f, rs1 = 0.f;
#pragma unroll
        for (int j = 0; j < 8; j++) {
            s[j][0] = __expf(s[j][0] - mn0);
            s[j][1] = __expf(s[j][1] - mn0);
            s[j][2] = __expf(s[j][2] - mn1);
            s[j][3] = __expf(s[j][3] - mn1);
            rs0 += s[j][0] + s[j][1];
            rs1 += s[j][2] + s[j][3];
        }
        rs0 += __shfl_xor_sync(0xffffffffu, rs0, 1);
        rs0 += __shfl_xor_sync(0xffffffffu, rs0, 2);
        rs1 += __shfl_xor_sync(0xffffffffu, rs1, 1);
        rs1 += __shfl_xor_sync(0xffffffffu, rs1, 2);
        l0 = l0 * a0 + rs0;
        l1 = l1 * a1 + rs1;
#pragma unroll
        for (int j = 0; j < 8; j++) {
            o[j][0] *= a0; o[j][1] *= a0;
            o[j][2] *= a1; o[j][3] *= a1;
        }

#pragma unroll
        for (int t = 0; t < 4; t++) {
            uint32_t pah[4], pal[4];
            pah[0] = pack_bf16_hi(s[2 * t][0], s[2 * t][1]);
            pal[0] = pack_bf16_lo(s[2 * t][0], s[2 * t][1]);
            pah[1] = pack_bf16_hi(s[2 * t][2], s[2 * t][3]);
            pal[1] = pack_bf16_lo(s[2 * t][2], s[2 * t][3]);
            pah[2] = pack_bf16_hi(s[2 * t + 1][0], s[2 * t + 1][1]);
            pal[2] = pack_bf16_lo(s[2 * t + 1][0], s[2 * t + 1][1]);
            pah[3] = pack_bf16_hi(s[2 * t + 1][2], s[2 * t + 1][3]);
            pal[3] = pack_bf16_lo(s[2 * t + 1][2], s[2 * t + 1][3]);
#pragma unroll
            for (int g = 0; g < 4; g++) {
                uint32_t ro = bo + (uint32_t)(g * 16 * ATT_PAD) + t * 32;
                uint32_t vh4[4], vl4[4];
                LDSM_X4(vh4, sb + SM_VT + ro);
                LDSM_X4(vl4, sb + SM_VT + ATT_KL + ro);
#pragma unroll
                for (int hf = 0; hf < 2; hf++) {
                    MMA16816(o[g * 2 + hf], pah, vh4[hf * 2], vh4[hf * 2 + 1]);
                    MMA16816(o[g * 2 + hf], pal, vh4[hf * 2], vh4[hf * 2 + 1]);
                    MMA16816(o[g * 2 + hf], pah, vl4[hf * 2], vl4[hf * 2 + 1]);
                }
            }
        }
        __syncthreads();
    }

    const float inv0 = 1.0f / l0, inv1 = 1.0f / l1;
    const int s0 = q0 + w * 16 + (lane >> 2);
    const int cl = (lane & 3) * 2;
#pragma unroll
    for (int j8 = 0; j8 < 8; j8++) {
        int col = h * 64 + j8 * 8 + cl;
        size_t i0 = (size_t)(b * SEQ + s0) * D_MODEL + col;
        size_t i1 = (size_t)(b * SEQ + s0 + 8) * D_MODEL + col;
        float v0 = o[j8][0] * inv0, v1 = o[j8][1] * inv0;
        float v2 = o[j8][2] * inv1, v3 = o[j8][3] * inv1;
        *(uint32_t*)(Chg + i0) = pack_bf16_hi(v0, v1);
        *(uint32_t*)(Clg + i0) = pack_bf16_lo(v0, v1);
        *(uint32_t*)(Chg + i1) = pack_bf16_hi(v2, v3);
        *(uint32_t*)(Clg + i1) = pack_bf16_lo(v2, v3);
    }
}

// ---------------------------------------------------------------------------
// Launch
// ---------------------------------------------------------------------------
extern "C" void kernel_launch(void* const* d_in, const int* in_sizes, int n_in,
                              void* d_out, int out_size)
{
    const float* x  = (const float*)d_in[0];
    const float* Wq = (const float*)d_in[1];
    const float* Wk = (const float*)d_in[2];
    const float* Wv = (const float*)d_in[3];
    const float* Wo = (const float*)d_in[4];
    float* out = (float*)d_out;

    __nv_bfloat16 *xhi, *xlo, *wthi, *wtlo, *qh, *ql, *kh, *kl, *vh, *vl, *ch, *cl;
    cudaGetSymbolAddress((void**)&xhi, g_xhi);
    cudaGetSymbolAddress((void**)&xlo, g_xlo);
    cudaGetSymbolAddress((void**)&wthi, g_wthi);
    cudaGetSymbolAddress((void**)&wtlo, g_wtlo);
    cudaGetSymbolAddress((void**)&qh, g_qh);
    cudaGetSymbolAddress((void**)&ql, g_ql);
    cudaGetSymbolAddress((void**)&kh, g_kh);
    cudaGetSymbolAddress((void**)&kl, g_kl);
    cudaGetSymbolAddress((void**)&vh, g_vh);
    cudaGetSymbolAddress((void**)&vl, g_vl);
    cudaGetSymbolAddress((void**)&ch, g_ch);
    cudaGetSymbolAddress((void**)&cl, g_cl);

    cudaFuncSetAttribute(gemm_mma_bf16x3, cudaFuncAttributeMaxDynamicSharedMemorySize, GEMM_SMEM);
    cudaFuncSetAttribute(attn_mma, cudaFuncAttributeMaxDynamicSharedMemorySize, ATT_SMEM);

    const size_t WSLOT = (size_t)D_MODEL * D_MODEL;
    dim3 tgrid(32, 32), tblk(32, 8);
    k_wsplit<<<tgrid, tblk>>>(Wq, wthi + 0 * WSLOT, wtlo + 0 * WSLOT);
    k_wsplit<<<tgrid, tblk>>>(Wk, wthi + 1 * WSLOT, wtlo + 1 * WSLOT);
    k_wsplit<<<tgrid, tblk>>>(Wv, wthi + 2 * WSLOT, wtlo + 2 * WSLOT);
    k_wsplit<<<tgrid, tblk>>>(Wo, wthi + 3 * WSLOT, wtlo + 3 * WSLOT);

    const int n4 = M_TOK * D_MODEL / 4;
    k_split<<<n4 / 256, 256>>>((const float4*)x, (uint2*)xhi, (uint2*)xlo, n4);

    dim3 gg(D_MODEL / 256, M_TOK / 128);   // (4, 256)
    gemm_mma_bf16x3<<<gg, 256, GEMM_SMEM>>>(xhi, xlo, wthi + 0 * WSLOT, wtlo + 0 * WSLOT,
                                            nullptr, qh, ql, 0.125f, 1,
                                            M_TOK, D_MODEL, D_MODEL);
    gemm_mma_bf16x3<<<gg, 256, GEMM_SMEM>>>(xhi, xlo, wthi + 1 * WSLOT, wtlo + 1 * WSLOT,
                                            nullptr, kh, kl, 1.0f, 1,
                                            M_TOK, D_MODEL, D_MODEL);
    gemm_mma_bf16x3<<<gg, 256, GEMM_SMEM>>>(xhi, xlo, wthi + 2 * WSLOT, wtlo + 2 * WSLOT,
                                            nullptr, vh, vl, 1.0f, 1,
                                            M_TOK, D_MODEL, D_MODEL);

    dim3 gAttn(SEQ / 128, BATCH * N_HEADS);   // (8, 512)
    attn_mma<<<gAttn, 256, ATT_SMEM>>>(qh, ql, kh, kl, vh, vl, ch, cl);

    gemm_mma_bf16x3<<<gg, 256, GEMM_SMEM>>>(ch, cl, wthi + 3 * WSLOT, wtlo + 3 * WSLOT,
                                            out, nullptr, nullptr, 1.0f, 0,
                                            M_TOK, D_MODEL, D_MODEL);
}

// round 6
// speedup vs baseline: 2.8671x; 1.2587x over previous
#include <cuda_runtime.h>
#include <cuda_bf16.h>
#include <math_constants.h>
#include <cstdint>

#define D_MODEL 1024
#define N_HEADS 16
#define HEAD_DIM 64
#define SEQ 1024
#define BATCH 32
#define M_TOK (BATCH * SEQ)   // 32768 tokens
#define SLOT_SZ ((size_t)M_TOK * D_MODEL)

// ---------------------------------------------------------------------------
// Scratch (alloc-free rule: __device__ globals).
// ---------------------------------------------------------------------------
__device__ __nv_bfloat16 g_xhi[SLOT_SZ];
__device__ __nv_bfloat16 g_xlo[SLOT_SZ];
__device__ __nv_bfloat16 g_wthi[(size_t)4 * D_MODEL * D_MODEL];
__device__ __nv_bfloat16 g_wtlo[(size_t)4 * D_MODEL * D_MODEL];
__device__ __nv_bfloat16 g_qkvh[3 * SLOT_SZ];
__device__ __nv_bfloat16 g_qkvl[3 * SLOT_SZ];
__device__ __nv_bfloat16 g_ch[SLOT_SZ];
__device__ __nv_bfloat16 g_cl[SLOT_SZ];

// ---------------------------------------------------------------------------
// PTX helpers — plain compute_103-legal only (mma.sync / ldmatrix / cp.async).
// ---------------------------------------------------------------------------
__device__ __forceinline__ uint32_t smem_to_u32(const void* p) {
    uint32_t a;
    asm("{ .reg .u64 t; cvta.to.shared.u64 t, %1; cvt.u32.u64 %0, t; }" : "=r"(a) : "l"(p));
    return a;
}

#define CP_ASYNC16(sa, gp) \
    asm volatile("cp.async.cg.shared.global [%0], [%1], 16;" :: "r"(sa), "l"(gp))
#define CP_COMMIT() asm volatile("cp.async.commit_group;" ::: "memory")
#define CP_WAIT1()  asm volatile("cp.async.wait_group 1;" ::: "memory")
#define CP_WAIT0()  asm volatile("cp.async.wait_group 0;" ::: "memory")

#define LDSM_X4(r, a) \
    asm volatile("ldmatrix.sync.aligned.m8n8.x4.shared.b16 {%0,%1,%2,%3}, [%4];" \
        : "=r"((r)[0]), "=r"((r)[1]), "=r"((r)[2]), "=r"((r)[3]) : "r"(a))

#define LDSM_X4_T(r, a) \
    asm volatile("ldmatrix.sync.aligned.m8n8.x4.trans.shared.b16 {%0,%1,%2,%3}, [%4];" \
        : "=r"((r)[0]), "=r"((r)[1]), "=r"((r)[2]), "=r"((r)[3]) : "r"(a))

#define MMA16816(c, a, b0v, b1v) \
    asm volatile("mma.sync.aligned.m16n8k16.row.col.f32.bf16.bf16.f32 " \
        "{%0,%1,%2,%3}, {%4,%5,%6,%7}, {%8,%9}, {%0,%1,%2,%3};" \
        : "+f"((c)[0]), "+f"((c)[1]), "+f"((c)[2]), "+f"((c)[3]) \
        : "r"((a)[0]), "r"((a)[1]), "r"((a)[2]), "r"((a)[3]), "r"(b0v), "r"(b1v))

__device__ __forceinline__ uint32_t pack_bf16_hi(float a, float b) {
    __nv_bfloat162 t;
    t.x = __float2bfloat16_rn(a);
    t.y = __float2bfloat16_rn(b);
    return *(uint32_t*)&t;
}
__device__ __forceinline__ uint32_t pack_bf16_lo(float a, float b) {
    __nv_bfloat16 ha = __float2bfloat16_rn(a), hb = __float2bfloat16_rn(b);
    __nv_bfloat162 t;
    t.x = __float2bfloat16_rn(a - __bfloat162float(ha));
    t.y = __float2bfloat16_rn(b - __bfloat162float(hb));
    return *(uint32_t*)&t;
}

// ---------------------------------------------------------------------------
// GEMM: C[M,N] = A[M,K] * B[N,K]^T, bf16x3 via mma.sync. Block 128x256,
// 8 warps (2x4), warp tile 64x64. K-chunk 32, THREE-stage cp.async pipeline,
// one __syncthreads per chunk.
// bfmode=0: fp32 out (row stride N). bfmode=1: bf16 hi/lo split out into
// slot-structured buffers (col>>10 selects slot; slot 0 scaled by `scale`).
// ---------------------------------------------------------------------------
#define PADB 80
#define STG_AL 10240                     // 128*80
#define STG_BH 20480
#define STG_BL 40960
#define STAGE_BYTES 61440
#define GEMM_SMEM (3 * STAGE_BYTES)      // 184320 B

__global__ __launch_bounds__(256, 1)
void gemm_mma_bf16x3(const __nv_bfloat16* __restrict__ Ahi, const __nv_bfloat16* __restrict__ Alo,
                     const __nv_bfloat16* __restrict__ Bhi, const __nv_bfloat16* __restrict__ Blo,
                     float* __restrict__ Cf,
                     __nv_bfloat16* __restrict__ Ohi, __nv_bfloat16* __restrict__ Olo,
                     float scale, int bfmode, int M, int N, int K)
{
    extern __shared__ char smc[];
    const uint32_t sbase = smem_to_u32(smc);
    const int tid = threadIdx.x;
    const int lane = tid & 31, wid = tid >> 5;
    const int wm = wid >> 2, wn = wid & 3;           // warp grid 2(M) x 4(N)
    const int m0 = blockIdx.y * 128, n0 = blockIdx.x * 256;

    float acc[4][8][4];
#pragma unroll
    for (int i = 0; i < 4; i++)
#pragma unroll
        for (int j = 0; j < 8; j++)
#pragma unroll
            for (int r = 0; r < 4; r++) acc[i][j][r] = 0.f;

    const uint32_t aoff = (uint32_t)((wm * 64 + (lane & 15)) * PADB + ((lane >> 4) & 1) * 16);
    const uint32_t boff = (uint32_t)((wn * 64 + (lane & 7) + ((lane >> 4) & 1) * 8) * PADB
                                     + ((lane >> 3) & 1) * 16);

    auto load_stage = [&](int ch, int st) {
        const uint32_t sb = sbase + st * STAGE_BYTES;
        const size_t k0 = (size_t)ch * 32;
#pragma unroll
        for (int i = 0; i < 2; i++) {
            int s = tid + 256 * i;
            int row = s >> 2, c = s & 3;
            uint32_t so = (uint32_t)(row * PADB + c * 16);
            size_t ga = ((size_t)(m0 + row) * K + k0) * 2 + c * 16;
            CP_ASYNC16(sb + so,          (const char*)Ahi + ga);
            CP_ASYNC16(sb + STG_AL + so, (const char*)Alo + ga);
        }
#pragma unroll
        for (int i = 0; i < 4; i++) {
            int s = tid + 256 * i;
            int row = s >> 2, c = s & 3;
            uint32_t so = (uint32_t)(row * PADB + c * 16);
            size_t gb = ((size_t)(n0 + row) * K + k0) * 2 + c * 16;
            CP_ASYNC16(sb + STG_BH + so, (const char*)Bhi + gb);
            CP_ASYNC16(sb + STG_BL + so, (const char*)Blo + gb);
        }
        CP_COMMIT();
    };

    const int NC = K / 32;
    load_stage(0, 0);
    load_stage(1, 1);

#pragma unroll 1
    for (int ch = 0; ch < NC; ch++) {
        const int st = ch % 3;
        if (ch + 1 < NC) { CP_WAIT1(); } else { CP_WAIT0(); }
        __syncthreads();

        const uint32_t sb = sbase + st * STAGE_BYTES;
#pragma unroll
        for (int ks = 0; ks < 2; ks++) {
            const uint32_t kb = ks * 32;
            uint32_t ah[4][4], al[4][4];
#pragma unroll
            for (int i = 0; i < 4; i++) {
                LDSM_X4(ah[i], sb + aoff + i * (16 * PADB) + kb);
                LDSM_X4(al[i], sb + STG_AL + aoff + i * (16 * PADB) + kb);
            }
#pragma unroll
            for (int j = 0; j < 4; j++) {
                uint32_t bh4[4], bl4[4];
                LDSM_X4(bh4, sb + STG_BH + boff + j * (16 * PADB) + kb);
                LDSM_X4(bl4, sb + STG_BL + boff + j * (16 * PADB) + kb);
#pragma unroll
                for (int i = 0; i < 4; i++)
#pragma unroll
                    for (int hf = 0; hf < 2; hf++) {
                        MMA16816(acc[i][j * 2 + hf], ah[i], bh4[hf * 2], bh4[hf * 2 + 1]);
                        MMA16816(acc[i][j * 2 + hf], al[i], bh4[hf * 2], bh4[hf * 2 + 1]);
                        MMA16816(acc[i][j * 2 + hf], ah[i], bl4[hf * 2], bl4[hf * 2 + 1]);
                    }
            }
        }
        if (ch + 2 < NC) load_stage(ch + 2, (ch + 2) % 3);
    }

    const int r = lane >> 2, cl = (lane & 3) * 2;
    if (!bfmode) {
#pragma unroll
        for (int i = 0; i < 4; i++)
#pragma unroll
            for (int j8 = 0; j8 < 8; j8++) {
                int row = m0 + wm * 64 + i * 16 + r;
                int col = n0 + wn * 64 + j8 * 8 + cl;
                *(float2*)(Cf + (size_t)row * N + col) =
                    make_float2(acc[i][j8][0], acc[i][j8][1]);
                *(float2*)(Cf + (size_t)(row + 8) * N + col) =
                    make_float2(acc[i][j8][2], acc[i][j8][3]);
            }
    } else {
#pragma unroll
        for (int i = 0; i < 4; i++)
#pragma unroll
            for (int j8 = 0; j8 < 8; j8++) {
                int row = m0 + wm * 64 + i * 16 + r;
                int col = n0 + wn * 64 + j8 * 8 + cl;
                int slot = col >> 10, cw = col & 1023;
                float sc = (slot == 0) ? scale : 1.0f;
                size_t base = (size_t)slot * SLOT_SZ;
                float v0 = acc[i][j8][0] * sc, v1 = acc[i][j8][1] * sc;
                float v2 = acc[i][j8][2] * sc, v3 = acc[i][j8][3] * sc;
                size_t i0 = base + (size_t)row * D_MODEL + cw;
                size_t i1 = base + (size_t)(row + 8) * D_MODEL + cw;
                *(uint32_t*)(Ohi + i0) = pack_bf16_hi(v0, v1);
                *(uint32_t*)(Olo + i0) = pack_bf16_lo(v0, v1);
                *(uint32_t*)(Ohi + i1) = pack_bf16_hi(v2, v3);
                *(uint32_t*)(Olo + i1) = pack_bf16_lo(v2, v3);
            }
    }
}

// ---------------------------------------------------------------------------
// Split fp32 -> (hi, lo) bf16, elementwise.
// ---------------------------------------------------------------------------
__global__ void k_split(const float4* __restrict__ in, uint2* __restrict__ hi,
                        uint2* __restrict__ lo, int n4)
{
    int i = blockIdx.x * blockDim.x + threadIdx.x;
    if (i >= n4) return;
    float4 v = in[i];
    float f[4] = {v.x, v.y, v.z, v.w};
    __nv_bfloat16 h[4], l[4];
#pragma unroll
    for (int j = 0; j < 4; j++) {
        h[j] = __float2bfloat16_rn(f[j]);
        l[j] = __float2bfloat16_rn(f[j] - __bfloat162float(h[j]));
    }
    hi[i] = *(uint2*)h;
    lo[i] = *(uint2*)l;
}

// Transpose + split weights: W[K,N] fp32 -> Wt_hi/lo[N,K] bf16.
__global__ void k_wsplit(const float* __restrict__ W, __nv_bfloat16* __restrict__ Th,
                         __nv_bfloat16* __restrict__ Tl)
{
    __shared__ float t[32][33];
    int k0 = blockIdx.x * 32, n0 = blockIdx.y * 32;
    int tx = threadIdx.x, ty = threadIdx.y;  // 32 x 8
#pragma unroll
    for (int i = 0; i < 4; i++)
        t[ty + 8 * i][tx] = W[(size_t)(k0 + ty + 8 * i) * D_MODEL + n0 + tx];
    __syncthreads();
#pragma unroll
    for (int i = 0; i < 4; i++) {
        float v = t[tx][ty + 8 * i];
        __nv_bfloat16 h = __float2bfloat16_rn(v);
        __nv_bfloat16 l = __float2bfloat16_rn(v - __bfloat162float(h));
        size_t o = (size_t)(n0 + ty + 8 * i) * D_MODEL + k0 + tx;
        Th[o] = h;
        Tl[o] = l;
    }
}

// ---------------------------------------------------------------------------
// Flash attention on tensor cores (bf16x3 QK^T and PV, fp32 softmax state).
// V consumed via ldmatrix.trans (no smem transpose). 3-stage KV pipeline,
// one __syncthreads per tile.
// ---------------------------------------------------------------------------
#define ATT_PAD 144
#define SMQ_H 0
#define SMQ_L (128 * ATT_PAD / 2)             // 9216 (Q rows are 64 dims = 128B+pad)
#define SM_STAGE0 (2 * 128 * ATT_PAD)          // placeholder below (recomputed)
// Q tile: 128 rows x 144B per hi/lo -> 18432 each
#undef SMQ_L
#undef SM_STAGE0
#define SMQ_L 18432
#define SM_STAGE0 36864
#define ATT_STG (4 * 64 * ATT_PAD)             // 36864: Kh,Kl,Vh,Vl
#define ATT_KL 9216
#define ATT_VH 18432
#define ATT_VL 27648
#define ATT_SMEM (SM_STAGE0 + 3 * ATT_STG)     // 147456

__global__ __launch_bounds__(256, 1)
void attn_mma(const __nv_bfloat16* __restrict__ QKVh, const __nv_bfloat16* __restrict__ QKVl,
              __nv_bfloat16* __restrict__ Chg, __nv_bfloat16* __restrict__ Clg)
{
    extern __shared__ char smc[];
    const uint32_t sb = smem_to_u32(smc);
    const int tid = threadIdx.x, lane = tid & 31, w = tid >> 5;
    const int b = blockIdx.y >> 4, h = blockIdx.y & 15;
    const int q0 = blockIdx.x * 128;
    const size_t rowB = (size_t)D_MODEL * 2;

    const char* Qh = (const char*)QKVh + ((size_t)(b * SEQ + q0) * D_MODEL + h * 64) * 2;
    const char* Ql = (const char*)QKVl + ((size_t)(b * SEQ + q0) * D_MODEL + h * 64) * 2;
    const char* Kh = (const char*)(QKVh + SLOT_SZ) + ((size_t)(b * SEQ) * D_MODEL + h * 64) * 2;
    const char* Kl = (const char*)(QKVl + SLOT_SZ) + ((size_t)(b * SEQ) * D_MODEL + h * 64) * 2;
    const char* Vh = (const char*)(QKVh + 2 * SLOT_SZ) + ((size_t)(b * SEQ) * D_MODEL + h * 64) * 2;
    const char* Vl = (const char*)(QKVl + 2 * SLOT_SZ) + ((size_t)(b * SEQ) * D_MODEL + h * 64) * 2;

    // Q tile (commit group)
    for (int i = tid; i < 1024; i += 256) {
        int r = i >> 3, c = i & 7;
        uint32_t so = (uint32_t)(r * ATT_PAD + c * 16);
        CP_ASYNC16(sb + SMQ_H + so, Qh + (size_t)r * rowB + c * 16);
        CP_ASYNC16(sb + SMQ_L + so, Ql + (size_t)r * rowB + c * 16);
    }
    CP_COMMIT();

    auto load_kv = [&](int tile, int st) {
        const uint32_t stB = sb + SM_STAGE0 + st * ATT_STG;
        const size_t n0b = (size_t)(tile * 64) * rowB;
        for (int i = tid; i < 512; i += 256) {
            int r = i >> 3, c = i & 7;
            size_t go = n0b + (size_t)r * rowB + c * 16;
            uint32_t so = (uint32_t)(r * ATT_PAD + c * 16);
            CP_ASYNC16(stB + so,          Kh + go);
            CP_ASYNC16(stB + ATT_KL + so, Kl + go);
            CP_ASYNC16(stB + ATT_VH + so, Vh + go);
            CP_ASYNC16(stB + ATT_VL + so, Vl + go);
        }
        CP_COMMIT();
    };

    load_kv(0, 0);
    CP_WAIT1();          // Q group complete
    __syncthreads();

    // Q A-fragments (loop-invariant)
    uint32_t qh[4][4], ql[4][4];
    {
        const uint32_t ao = (uint32_t)((w * 16 + (lane & 15)) * ATT_PAD + ((lane >> 4) & 1) * 16);
#pragma unroll
        for (int t = 0; t < 4; t++) {
            LDSM_X4(qh[t], sb + SMQ_H + ao + t * 32);
            LDSM_X4(ql[t], sb + SMQ_L + ao + t * 32);
        }
    }
    load_kv(1, 1);

    float o[8][4];
#pragma unroll
    for (int j = 0; j < 8; j++)
#pragma unroll
        for (int r = 0; r < 4; r++) o[j][r] = 0.f;
    float m0 = -CUDART_INF_F, m1 = -CUDART_INF_F, l0 = 0.f, l1 = 0.f;

    // K (non-trans) lane base; V (trans) lane base
    const uint32_t bo = (uint32_t)(((lane & 7) + ((lane >> 4) & 1) * 8) * ATT_PAD
                                   + ((lane >> 3) & 1) * 16);
    const uint32_t vo = (uint32_t)(((lane & 7) + ((lane >> 3) & 1) * 8) * ATT_PAD
                                   + ((lane >> 4) & 1) * 16);

#pragma unroll 1
    for (int tile = 0; tile < 16; tile++) {
        const int st = tile % 3;
        if (tile + 1 < 16) { CP_WAIT1(); } else { CP_WAIT0(); }
        __syncthreads();

        const uint32_t stB = SM_STAGE0 + st * ATT_STG;
        const uint32_t sbK = sb + stB;

        // S = Q K^T
        float s[8][4];
#pragma unroll
        for (int j = 0; j < 8; j++)
#pragma unroll
            for (int r = 0; r < 4; r++) s[j][r] = 0.f;

#pragma unroll
        for (int t = 0; t < 4; t++)
#pragma unroll
            for (int g = 0; g < 4; g++) {
                uint32_t ro = bo + (uint32_t)(g * 16 * ATT_PAD) + t * 32;
                uint32_t kh4[4], kl4[4];
                LDSM_X4(kh4, sbK + ro);
                LDSM_X4(kl4, sbK + ATT_KL + ro);
#pragma unroll
                for (int hf = 0; hf < 2; hf++) {
                    MMA16816(s[g * 2 + hf], qh[t], kh4[hf * 2], kh4[hf * 2 + 1]);
                    MMA16816(s[g * 2 + hf], ql[t], kh4[hf * 2], kh4[hf * 2 + 1]);
                    MMA16816(s[g * 2 + hf], qh[t], kl4[hf * 2], kl4[hf * 2 + 1]);
                }
            }

        // Online softmax
        float mx0 = -CUDART_INF_F, mx1 = -CUDART_INF_F;
#pragma unroll
        for (int j = 0; j < 8; j++) {
            mx0 = fmaxf(mx0, fmaxf(s[j][0], s[j][1]));
            mx1 = fmaxf(mx1, fmaxf(s[j][2], s[j][3]));
        }
        mx0 = fmaxf(mx0, __shfl_xor_sync(0xffffffffu, mx0, 1));
        mx0 = fmaxf(mx0, __shfl_xor_sync(0xffffffffu, mx0, 2));
        mx1 = fmaxf(mx1, __shfl_xor_sync(0xffffffffu, mx1, 1));
        mx1 = fmaxf(mx1, __shfl_xor_sync(0xffffffffu, mx1, 2));
        float mn0 = fmaxf(m0, mx0), mn1 = fmaxf(m1, mx1);
        float a0 = __expf(m0 - mn0), a1 = __expf(m1 - mn1);
        m0 = mn0; m1 = mn1;
        float rs0 = 0.f, rs1 = 0.f;
#pragma unroll
        for (int j = 0; j < 8; j++) {
            s[j][0] = __expf(s[j][0] - mn0);
            s[j][1] = __expf(s[j][1] - mn0);
            s[j][2] = __expf(s[j][2] - mn1);
            s[j][3] = __expf(s[j][3] - mn1);
            rs0 += s[j][0] + s[j][1];
            rs1 += s[j][2] + s[j][3];
        }
        rs0 += __shfl_xor_sync(0xffffffffu, rs0, 1);
        rs0 += __shfl_xor_sync(0xffffffffu, rs0, 2);
        rs1 += __shfl_xor_sync(0xffffffffu, rs1, 1);
        rs1 += __shfl_xor_sync(0xffffffffu, rs1, 2);
        l0 = l0 * a0 + rs0;
        l1 = l1 * a1 + rs1;
#pragma unroll
        for (int j = 0; j < 8; j++) {
            o[j][0] *= a0; o[j][1] *= a0;
            o[j][2] *= a1; o[j][3] *= a1;
        }

        // O += P V  (V B-fragments via trans-ldmatrix from row-major V)
#pragma unroll
        for (int t = 0; t < 4; t++) {
            uint32_t pah[4], pal[4];
            pah[0] = pack_bf16_hi(s[2 * t][0], s[2 * t][1]);
            pal[0] = pack_bf16_lo(s[2 * t][0], s[2 * t][1]);
            pah[1] = pack_bf16_hi(s[2 * t][2], s[2 * t][3]);
            pal[1] = pack_bf16_lo(s[2 * t][2], s[2 * t][3]);
            pah[2] = pack_bf16_hi(s[2 * t + 1][0], s[2 * t + 1][1]);
            pal[2] = pack_bf16_lo(s[2 * t + 1][0], s[2 * t + 1][1]);
            pah[3] = pack_bf16_hi(s[2 * t + 1][2], s[2 * t + 1][3]);
            pal[3] = pack_bf16_lo(s[2 * t + 1][2], s[2 * t + 1][3]);
#pragma unroll
            for (int g = 0; g < 4; g++) {
                uint32_t ro = vo + (uint32_t)(t * 16 * ATT_PAD) + g * 32;
                uint32_t vh4[4], vl4[4];
                LDSM_X4_T(vh4, sbK + ATT_VH + ro);
                LDSM_X4_T(vl4, sbK + ATT_VL + ro);
#pragma unroll
                for (int hf = 0; hf < 2; hf++) {
                    MMA16816(o[g * 2 + hf], pah, vh4[hf * 2], vh4[hf * 2 + 1]);
                    MMA16816(o[g * 2 + hf], pal, vh4[hf * 2], vh4[hf * 2 + 1]);
                    MMA16816(o[g * 2 + hf], pah, vl4[hf * 2], vl4[hf * 2 + 1]);
                }
            }
        }
        if (tile + 2 < 16) load_kv(tile + 2, (tile + 2) % 3);
    }

    // Epilogue: normalize, split hi/lo, store ctx bf16.
    const float inv0 = 1.0f / l0, inv1 = 1.0f / l1;
    const int s0 = q0 + w * 16 + (lane >> 2);
    const int cl = (lane & 3) * 2;
#pragma unroll
    for (int j8 = 0; j8 < 8; j8++) {
        int col = h * 64 + j8 * 8 + cl;
        size_t i0 = (size_t)(b * SEQ + s0) * D_MODEL + col;
        size_t i1 = (size_t)(b * SEQ + s0 + 8) * D_MODEL + col;
        float v0 = o[j8][0] * inv0, v1 = o[j8][1] * inv0;
        float v2 = o[j8][2] * inv1, v3 = o[j8][3] * inv1;
        *(uint32_t*)(Chg + i0) = pack_bf16_hi(v0, v1);
        *(uint32_t*)(Clg + i0) = pack_bf16_lo(v0, v1);
        *(uint32_t*)(Chg + i1) = pack_bf16_hi(v2, v3);
        *(uint32_t*)(Clg + i1) = pack_bf16_lo(v2, v3);
    }
}

// ---------------------------------------------------------------------------
// Launch
// ---------------------------------------------------------------------------
extern "C" void kernel_launch(void* const* d_in, const int* in_sizes, int n_in,
                              void* d_out, int out_size)
{
    const float* x  = (const float*)d_in[0];
    const float* Wq = (const float*)d_in[1];
    const float* Wk = (const float*)d_in[2];
    const float* Wv = (const float*)d_in[3];
    const float* Wo = (const float*)d_in[4];
    float* out = (float*)d_out;

    __nv_bfloat16 *xhi, *xlo, *wthi, *wtlo, *qkvh, *qkvl, *ch, *cl;
    cudaGetSymbolAddress((void**)&xhi, g_xhi);
    cudaGetSymbolAddress((void**)&xlo, g_xlo);
    cudaGetSymbolAddress((void**)&wthi, g_wthi);
    cudaGetSymbolAddress((void**)&wtlo, g_wtlo);
    cudaGetSymbolAddress((void**)&qkvh, g_qkvh);
    cudaGetSymbolAddress((void**)&qkvl, g_qkvl);
    cudaGetSymbolAddress((void**)&ch, g_ch);
    cudaGetSymbolAddress((void**)&cl, g_cl);

    cudaFuncSetAttribute(gemm_mma_bf16x3, cudaFuncAttributeMaxDynamicSharedMemorySize, GEMM_SMEM);
    cudaFuncSetAttribute(attn_mma, cudaFuncAttributeMaxDynamicSharedMemorySize, ATT_SMEM);

    const size_t WSLOT = (size_t)D_MODEL * D_MODEL;
    dim3 tgrid(32, 32), tblk(32, 8);
    k_wsplit<<<tgrid, tblk>>>(Wq, wthi + 0 * WSLOT, wtlo + 0 * WSLOT);
    k_wsplit<<<tgrid, tblk>>>(Wk, wthi + 1 * WSLOT, wtlo + 1 * WSLOT);
    k_wsplit<<<tgrid, tblk>>>(Wv, wthi + 2 * WSLOT, wtlo + 2 * WSLOT);
    k_wsplit<<<tgrid, tblk>>>(Wo, wthi + 3 * WSLOT, wtlo + 3 * WSLOT);

    const int n4 = M_TOK * D_MODEL / 4;
    k_split<<<n4 / 256, 256>>>((const float4*)x, (uint2*)xhi, (uint2*)xlo, n4);

    // Fused QKV projection: N = 3072 (weight slots 0..2 contiguous).
    dim3 gqkv(3 * D_MODEL / 256, M_TOK / 128);   // (12, 256)
    gemm_mma_bf16x3<<<gqkv, 256, GEMM_SMEM>>>(xhi, xlo, wthi, wtlo,
                                              nullptr, qkvh, qkvl, 0.125f, 1,
                                              M_TOK, 3 * D_MODEL, D_MODEL);

    dim3 gAttn(SEQ / 128, BATCH * N_HEADS);   // (8, 512)
    attn_mma<<<gAttn, 256, ATT_SMEM>>>(qkvh, qkvl, ch, cl);

    dim3 go(D_MODEL / 256, M_TOK / 128);      // (4, 256)
    gemm_mma_bf16x3<<<go, 256, GEMM_SMEM>>>(ch, cl, wthi + 3 * WSLOT, wtlo + 3 * WSLOT,
                                            out, nullptr, nullptr, 1.0f, 0,
                                            M_TOK, D_MODEL, D_MODEL);
}